// round 2
// baseline (speedup 1.0000x reference)
#include <cuda_runtime.h>
#include <math.h>
#include <stdint.h>

// Problem constants
#define BB   2
#define LL   4096
#define DIMD 1024
#define NH   16
#define HD   64
#define MROWS (BB * LL)          // 8192

// ---------------------------------------------------------------------------
// Scratch (no cudaMalloc allowed) : __device__ globals
// ---------------------------------------------------------------------------
__device__ float g_xp[(size_t)MROWS * 2048];  // [x_inner | x_gate]
__device__ float g_q [(size_t)MROWS * 1024];
__device__ float g_k [(size_t)MROWS * 1024];
__device__ float g_v [(size_t)MROWS * 1024];
__device__ float g_i [(size_t)MROWS * 1024];
__device__ float g_f [(size_t)MROWS * 1024];
__device__ float g_o [(size_t)MROWS * 1024];
__device__ float g_h [(size_t)MROWS * 1024];

// ---------------------------------------------------------------------------
// SGEMM:  C[M,N] = A[M,K] @ B[N,K]^T   (both K-major, "NT")
// BM=BN=128, BK=8, 256 threads, 8x8 per-thread tile.
// ACT: 0 = none, 1 = exp(x + bias), 2 = sigmoid(x + bias)
// grid = (N/128, M/128)
// ---------------------------------------------------------------------------
template <int ACT>
__global__ void __launch_bounds__(256, 2)
sgemm_nt(const float* __restrict__ A, int lda,
         const float* __restrict__ B,           // [N, K], row stride K
         const float* __restrict__ bias,
         float* __restrict__ C, int ldc,
         int K)
{
    __shared__ float As[8][128];
    __shared__ float Bs[8][128];

    const int tid  = threadIdx.x;
    const int tr   = tid >> 4;          // 0..15 (row group)
    const int tc   = tid & 15;          // 0..15 (col group)
    const int lrow = tid >> 1;          // 0..127
    const int lcol = (tid & 1) << 2;    // 0 or 4

    const float* Ap = A + (size_t)(blockIdx.y * 128 + lrow) * lda + lcol;
    const float* Bp = B + (size_t)(blockIdx.x * 128 + lrow) * K   + lcol;

    float acc[8][8] = {};

    for (int k0 = 0; k0 < K; k0 += 8) {
        float4 a4 = *(const float4*)(Ap + k0);
        float4 b4 = *(const float4*)(Bp + k0);
        As[lcol + 0][lrow] = a4.x; As[lcol + 1][lrow] = a4.y;
        As[lcol + 2][lrow] = a4.z; As[lcol + 3][lrow] = a4.w;
        Bs[lcol + 0][lrow] = b4.x; Bs[lcol + 1][lrow] = b4.y;
        Bs[lcol + 2][lrow] = b4.z; Bs[lcol + 3][lrow] = b4.w;
        __syncthreads();

#pragma unroll
        for (int kk = 0; kk < 8; kk++) {
            float4 m0 = *(const float4*)&As[kk][tr * 8];
            float4 m1 = *(const float4*)&As[kk][tr * 8 + 4];
            float4 n0 = *(const float4*)&Bs[kk][tc * 8];
            float4 n1 = *(const float4*)&Bs[kk][tc * 8 + 4];
            float rm[8] = {m0.x, m0.y, m0.z, m0.w, m1.x, m1.y, m1.z, m1.w};
            float rn[8] = {n0.x, n0.y, n0.z, n0.w, n1.x, n1.y, n1.z, n1.w};
#pragma unroll
            for (int i = 0; i < 8; i++)
#pragma unroll
                for (int j = 0; j < 8; j++)
                    acc[i][j] = fmaf(rm[i], rn[j], acc[i][j]);
        }
        __syncthreads();
    }

    const int crow0 = blockIdx.y * 128 + tr * 8;
    const int ccol0 = blockIdx.x * 128 + tc * 8;
#pragma unroll
    for (int i = 0; i < 8; i++) {
#pragma unroll
        for (int j4 = 0; j4 < 8; j4 += 4) {
            float4 vo;
            float* vp = &vo.x;
#pragma unroll
            for (int j = 0; j < 4; j++) {
                float vval = acc[i][j4 + j];
                int col = ccol0 + j4 + j;
                if (ACT == 1)      vval = expf(vval + bias[col]);
                else if (ACT == 2) vval = 1.0f / (1.0f + expf(-(vval + bias[col])));
                vp[j] = vval;
            }
            *(float4*)&C[(size_t)(crow0 + i) * ldc + ccol0 + j4] = vo;
        }
    }
}

// ---------------------------------------------------------------------------
// RMSNorm over head_dim=64, one warp per (row, head). In place.
// ---------------------------------------------------------------------------
__global__ void rmsnorm_k(float* __restrict__ x, const float* __restrict__ w, int nrows)
{
    int warp = (blockIdx.x * blockDim.x + threadIdx.x) >> 5;
    int lane = threadIdx.x & 31;
    if (warp >= nrows) return;
    float* p = x + (size_t)warp * 64;
    float a = p[lane], b = p[lane + 32];
    float ss = a * a + b * b;
#pragma unroll
    for (int o = 16; o; o >>= 1) ss += __shfl_xor_sync(0xffffffffu, ss, o);
    float s = rsqrtf(ss * (1.0f / 64.0f) + 1e-6f);
    p[lane]      = a * s * w[lane];
    p[lane + 32] = b * s * w[lane + 32];
}

// ---------------------------------------------------------------------------
// Sequential mLSTM scan. One block per (b,h). 128 threads:
//   warp r (0..3) owns rows d = r*16 .. r*16+15 of state C (64x64)
//   lane c owns columns c and c+32  -> 32 C-registers per thread
// Threads 0..63 additionally own n[d] (d = tid) + den reduction.
// Per-step inputs staged via cp.async double buffering (7 x 64 floats).
// Output fused with og and sigmoid(x_gate).
// ---------------------------------------------------------------------------
__device__ __forceinline__ void cp16(uint32_t s, const void* g)
{
    asm volatile("cp.async.ca.shared.global [%0], [%1], 16;\n" :: "r"(s), "l"(g));
}

__global__ void __launch_bounds__(128, 1)
mlstm_scan(const float* __restrict__ q, const float* __restrict__ k,
           const float* __restrict__ v, const float* __restrict__ ig,
           const float* __restrict__ fg, const float* __restrict__ og,
           const float* __restrict__ xp,   // gate half at col offset 1024, stride 2048
           float* __restrict__ hout)
{
    __shared__ float stage[2][7][64];
    __shared__ float red[4][64];
    __shared__ float denp[2];

    const int tid = threadIdx.x;
    const int b   = blockIdx.x >> 4;
    const int h   = blockIdx.x & 15;
    const size_t base  = ((size_t)b * LL) * 1024 + (size_t)h * 64;
    const size_t baseg = ((size_t)b * LL) * 2048 + 1024 + (size_t)h * 64;

    const float* srcs[8] = { q + base, k + base, v + base, ig + base,
                             fg + base, og + base, xp + baseg, q + base /*pad*/ };

    const int  arr    = tid >> 4;       // 0..7
    const int  ch     = tid & 15;       // 16B chunk within array
    const bool loader = (tid < 112);
    const float* mySrc    = srcs[arr] + ch * 4;
    const size_t mystride = (arr == 6) ? 2048 : 1024;
    const uint32_t mydst0 = (uint32_t)__cvta_generic_to_shared(&stage[0][0][0]) + (arr * 64 + ch * 4) * 4;
    const uint32_t mydst1 = mydst0 + 7 * 64 * 4;

    // prologue: stage t = 0 into buffer 0
    if (loader) cp16(mydst0, mySrc);
    asm volatile("cp.async.commit_group;\n");

    const int r = tid >> 5;   // warp -> row group
    const int c = tid & 31;   // column (and c+32)
    float C0[16], C1[16];
#pragma unroll
    for (int i = 0; i < 16; i++) { C0[i] = 0.0f; C1[i] = 0.0f; }
    float nreg = 0.0f;

    float* outp = hout + base;

    for (int t = 0; t < LL; t++) {
        asm volatile("cp.async.wait_group 0;\n" ::: "memory");
        __syncthreads();
        const int cur = t & 1;

        // prefetch t+1 into the other buffer
        if (t + 1 < LL && loader)
            cp16(cur ? mydst0 : mydst1, mySrc + (size_t)(t + 1) * mystride);
        asm volatile("cp.async.commit_group;\n");

        const float* S   = &stage[cur][0][0];
        const float* qs  = S;
        const float* ks  = S + 64;
        const float* vs  = S + 128;
        const float* is_ = S + 192;
        const float* fs  = S + 256;
        const float* ogs = S + 320;
        const float* xgs = S + 384;

        float v0 = vs[c], v1 = vs[c + 32];
        float pn0 = 0.0f, pn1 = 0.0f;

#define ROWOP(ff, qq, aa, idx) { float _a = (aa);                              \
        C0[idx] = fmaf((ff), C0[idx], _a * v0); pn0 = fmaf((qq), C0[idx], pn0);\
        C1[idx] = fmaf((ff), C1[idx], _a * v1); pn1 = fmaf((qq), C1[idx], pn1); }

#pragma unroll
        for (int dd = 0; dd < 16; dd += 4) {
            int d = r * 16 + dd;
            float4 f4 = *(const float4*)&fs[d];
            float4 q4 = *(const float4*)&qs[d];
            float4 i4 = *(const float4*)&is_[d];
            float4 k4 = *(const float4*)&ks[d];
            ROWOP(f4.x, q4.x, i4.x * k4.x, dd + 0);
            ROWOP(f4.y, q4.y, i4.y * k4.y, dd + 1);
            ROWOP(f4.z, q4.z, i4.z * k4.z, dd + 2);
            ROWOP(f4.w, q4.w, i4.w * k4.w, dd + 3);
        }
#undef ROWOP

        red[r][c]      = pn0;
        red[r][c + 32] = pn1;

        if (tid < 64) {
            float a = is_[tid] * ks[tid];
            nreg = fmaf(fs[tid], nreg, a);
            float dp = qs[tid] * nreg;
#pragma unroll
            for (int o = 16; o; o >>= 1) dp += __shfl_xor_sync(0xffffffffu, dp, o);
            if ((tid & 31) == 0) denp[tid >> 5] = dp;
        }
        __syncthreads();

        if (tid < 64) {
            float num = red[0][tid] + red[1][tid] + red[2][tid] + red[3][tid];
            float den = fmaxf(denp[0] + denp[1], 1.0f);
            float ov  = (num / den) * ogs[tid] * (1.0f / (1.0f + expf(-xgs[tid])));
            outp[(size_t)t * 1024 + tid] = ov;
        }
    }
}

// ---------------------------------------------------------------------------
// Launch
// ---------------------------------------------------------------------------
extern "C" void kernel_launch(void* const* d_in, const int* in_sizes, int n_in,
                              void* d_out, int out_size)
{
    const float* x     = (const float*)d_in[0];
    const float* w_in  = (const float*)d_in[1];
    const float* w_q   = (const float*)d_in[2];
    const float* w_k   = (const float*)d_in[3];
    const float* w_v   = (const float*)d_in[4];
    const float* w_i   = (const float*)d_in[5];
    const float* b_i   = (const float*)d_in[6];
    const float* w_f   = (const float*)d_in[7];
    const float* b_f   = (const float*)d_in[8];
    const float* w_o   = (const float*)d_in[9];
    const float* b_o   = (const float*)d_in[10];
    const float* w_qn  = (const float*)d_in[11];
    const float* w_kn  = (const float*)d_in[12];
    const float* w_out = (const float*)d_in[13];
    float* out = (float*)d_out;

    float *xp, *qb, *kb, *vb, *ib, *fb, *ob, *hb;
    cudaGetSymbolAddress((void**)&xp, g_xp);
    cudaGetSymbolAddress((void**)&qb, g_q);
    cudaGetSymbolAddress((void**)&kb, g_k);
    cudaGetSymbolAddress((void**)&vb, g_v);
    cudaGetSymbolAddress((void**)&ib, g_i);
    cudaGetSymbolAddress((void**)&fb, g_f);
    cudaGetSymbolAddress((void**)&ob, g_o);
    cudaGetSymbolAddress((void**)&hb, g_h);

    dim3 blk(256);
    dim3 gIn(2048 / 128, MROWS / 128);   // in_proj: N=2048
    dim3 gSq(1024 / 128, MROWS / 128);   // square GEMMs: N=1024

    // 1) xp = x @ in_proj_w.T  -> [x_inner | x_gate]
    sgemm_nt<0><<<gIn, blk>>>(x, DIMD, w_in, nullptr, xp, 2048, DIMD);

    // 2) projections from x_inner (= xp with lda=2048)
    sgemm_nt<0><<<gSq, blk>>>(xp, 2048, w_q, nullptr, qb, 1024, DIMD);
    sgemm_nt<0><<<gSq, blk>>>(xp, 2048, w_k, nullptr, kb, 1024, DIMD);
    sgemm_nt<0><<<gSq, blk>>>(xp, 2048, w_v, nullptr, vb, 1024, DIMD);
    sgemm_nt<1><<<gSq, blk>>>(xp, 2048, w_i, b_i,    ib, 1024, DIMD); // exp gate
    sgemm_nt<2><<<gSq, blk>>>(xp, 2048, w_f, b_f,    fb, 1024, DIMD); // sigmoid
    sgemm_nt<2><<<gSq, blk>>>(xp, 2048, w_o, b_o,    ob, 1024, DIMD); // sigmoid

    // 3) per-head RMSNorm on q, k
    const int headrows = MROWS * NH;                 // 131072
    rmsnorm_k<<<headrows / 8, 256>>>(qb, w_qn, headrows);
    rmsnorm_k<<<headrows / 8, 256>>>(kb, w_kn, headrows);

    // 4) recurrent scan (fused og * sigmoid(x_gate))
    mlstm_scan<<<BB * NH, 128>>>(qb, kb, vb, ib, fb, ob, xp, hb);

    // 5) out = h @ out_proj_w.T
    sgemm_nt<0><<<gSq, blk>>>(hb, 1024, w_out, nullptr, out, 1024, DIMD);
}

// round 4
// speedup vs baseline: 1.4981x; 1.4981x over previous
#include <cuda_runtime.h>
#include <cuda_bf16.h>
#include <math.h>
#include <stdint.h>

// Problem constants
#define BB   2
#define LL   4096
#define DIMD 1024
#define NH   16
#define HD   64
#define MROWS (BB * LL)          // 8192
#define KDIM 1024                // every GEMM has K=1024

// ---------------------------------------------------------------------------
// Scratch
// ---------------------------------------------------------------------------
__device__ float g_xp[(size_t)MROWS * 2048];
__device__ float g_q [(size_t)MROWS * 1024];
__device__ float g_k [(size_t)MROWS * 1024];
__device__ float g_v [(size_t)MROWS * 1024];
__device__ float g_i [(size_t)MROWS * 1024];
__device__ float g_f [(size_t)MROWS * 1024];
__device__ float g_o [(size_t)MROWS * 1024];
__device__ float g_h [(size_t)MROWS * 1024];

// ---------------------------------------------------------------------------
// mma.sync split-bf16 GEMM:  C[M,N] = A[M,K] @ B[N,K]^T, fp32 in/out, K=1024
// CTA tile 128x128, BK=32, 256 threads = 8 warps (4 along M x 2 along N),
// warp tile 32x64. A,B split into bf16 hi+lo; 3 HMMAs (hh, hl, lh) per pair.
// smem per stage: Ahi|Alo|Bhi|Blo, each [128][40] bf16 (pad 8 -> 80B rows,
// conflict-free for ldmatrix). Double buffered: 2 x 40960 B = 80 KB.
// ---------------------------------------------------------------------------
#define BK 32
#define ROWB 80                      // bytes per smem row (40 bf16)
#define SEC  10240                   // bytes per matrix section (128*80)
#define STAGE_BYTES (4 * SEC)        // 40960
#define GEMM_SMEM (2 * STAGE_BYTES)  // 81920

#define LDSM_X4(r0, r1, r2, r3, addr) \
    asm volatile("ldmatrix.sync.aligned.m8n8.x4.shared.b16 {%0,%1,%2,%3}, [%4];" \
                 : "=r"(r0), "=r"(r1), "=r"(r2), "=r"(r3) : "r"(addr))

#define MMA_BF16(d, a, b0, b1) \
    asm volatile("mma.sync.aligned.m16n8k16.row.col.f32.bf16.bf16.f32 " \
                 "{%0,%1,%2,%3}, {%4,%5,%6,%7}, {%8,%9}, {%0,%1,%2,%3};" \
                 : "+f"((d)[0]), "+f"((d)[1]), "+f"((d)[2]), "+f"((d)[3]) \
                 : "r"((a)[0]), "r"((a)[1]), "r"((a)[2]), "r"((a)[3]), \
                   "r"(b0), "r"(b1))

__device__ __forceinline__ uint32_t packbf(float x, float y) {
    __nv_bfloat16 bx = __float2bfloat16_rn(x);
    __nv_bfloat16 by = __float2bfloat16_rn(y);
    return (uint32_t)__bfloat16_as_ushort(bx) | ((uint32_t)__bfloat16_as_ushort(by) << 16);
}
__device__ __forceinline__ uint32_t packlo(float x, float y) {
    __nv_bfloat16 bx = __float2bfloat16_rn(x);
    __nv_bfloat16 by = __float2bfloat16_rn(y);
    float rx = x - __bfloat162float(bx);
    float ry = y - __bfloat162float(by);
    return packbf(rx, ry);
}
__device__ __forceinline__ void sts64(uint32_t a, uint32_t v0, uint32_t v1) {
    asm volatile("st.shared.v2.b32 [%0], {%1, %2};" :: "r"(a), "r"(v0), "r"(v1) : "memory");
}

template <int ACT>
__global__ void __launch_bounds__(256, 1)
gemm_mma(const float* __restrict__ A, int lda,
         const float* __restrict__ B,
         const float* __restrict__ bias,
         float* __restrict__ C, int ldc)
{
    extern __shared__ __align__(128) char smem[];
    const uint32_t sbase = (uint32_t)__cvta_generic_to_shared(smem);

    const int tid  = threadIdx.x;
    const int w    = tid >> 5;
    const int lane = tid & 31;
    const int wm   = w & 3;          // warp row group (32 rows)
    const int wn   = w >> 2;         // warp col group (64 cols)

    const int m0 = blockIdx.y * 128;
    const int n0 = blockIdx.x * 128;

    // ---- loader mapping: 2 threads per row, 16 k-floats each ----
    const int arow = tid >> 1;
    const int ak   = (tid & 1) << 4;   // 0 or 16
    const float* Ag = A + (size_t)(m0 + arow) * lda + ak;
    const float* Bg = B + (size_t)(n0 + arow) * KDIM + ak;
    const uint32_t sA = sbase + (uint32_t)(arow * ROWB + ak * 2);
    const uint32_t sB = sA + 2 * SEC;

    float4 ra[4], rb[4];
    auto LDG = [&](int k0) {
#pragma unroll
        for (int i = 0; i < 4; i++) {
            ra[i] = *(const float4*)(Ag + k0 + 4 * i);
            rb[i] = *(const float4*)(Bg + k0 + 4 * i);
        }
    };
    auto STS = [&](int buf) {
        const uint32_t bo = (uint32_t)(buf * STAGE_BYTES);
#pragma unroll
        for (int i = 0; i < 4; i++) {
            sts64(sA + bo + 8 * i,       packbf(ra[i].x, ra[i].y), packbf(ra[i].z, ra[i].w));
            sts64(sA + bo + SEC + 8 * i, packlo(ra[i].x, ra[i].y), packlo(ra[i].z, ra[i].w));
            sts64(sB + bo + 8 * i,       packbf(rb[i].x, rb[i].y), packbf(rb[i].z, rb[i].w));
            sts64(sB + bo + SEC + 8 * i, packlo(rb[i].x, rb[i].y), packlo(rb[i].z, rb[i].w));
        }
    };

    // ---- ldmatrix per-lane address components ----
    const int a_r = (lane & 7) + ((lane >> 3) & 1) * 8;   // row within 16
    const int a_k = ((lane >> 4) & 1) * 8;                // k offset 0/8
    const int g   = lane >> 3;
    const int b_r = ((g >> 1) * 8) + (lane & 7);          // n within 16
    const int b_k = (g & 1) * 8;

    const uint32_t aAddr0 = sbase + (uint32_t)((wm * 32 + a_r) * ROWB + a_k * 2);
    const uint32_t bAddr0 = sbase + 2 * SEC + (uint32_t)((wn * 64 + b_r) * ROWB + b_k * 2);

    float acc[2][8][4] = {};

    LDG(0);
    STS(0);
    __syncthreads();

    const int S = KDIM / BK;   // 32
    for (int s = 0; s < S; s++) {
        if (s + 1 < S) LDG((s + 1) * BK);
        const uint32_t bo = (uint32_t)((s & 1) * STAGE_BYTES);

#pragma unroll
        for (int kb = 0; kb < 2; kb++) {          // two k16 steps
            const uint32_t ko = (uint32_t)(kb * 32);  // 16 bf16 = 32 bytes
            uint32_t Ah[2][4], Al[2][4], Bh[4][4], Bl[4][4];
#pragma unroll
            for (int mi = 0; mi < 2; mi++) {
                uint32_t aa = aAddr0 + bo + ko + (uint32_t)(mi * 16 * ROWB);
                LDSM_X4(Ah[mi][0], Ah[mi][1], Ah[mi][2], Ah[mi][3], aa);
                LDSM_X4(Al[mi][0], Al[mi][1], Al[mi][2], Al[mi][3], aa + SEC);
            }
#pragma unroll
            for (int gi = 0; gi < 4; gi++) {
                uint32_t ba = bAddr0 + bo + ko + (uint32_t)(gi * 16 * ROWB);
                LDSM_X4(Bh[gi][0], Bh[gi][1], Bh[gi][2], Bh[gi][3], ba);
                LDSM_X4(Bl[gi][0], Bl[gi][1], Bl[gi][2], Bl[gi][3], ba + SEC);
            }
#pragma unroll
            for (int mi = 0; mi < 2; mi++)
#pragma unroll
                for (int gi = 0; gi < 4; gi++)
#pragma unroll
                    for (int hf = 0; hf < 2; hf++) {
                        float* d = acc[mi][gi * 2 + hf];
                        MMA_BF16(d, Ah[mi], Bh[gi][2 * hf], Bh[gi][2 * hf + 1]);
                        MMA_BF16(d, Ah[mi], Bl[gi][2 * hf], Bl[gi][2 * hf + 1]);
                        MMA_BF16(d, Al[mi], Bh[gi][2 * hf], Bh[gi][2 * hf + 1]);
                    }
        }

        if (s + 1 < S) {
            STS((s + 1) & 1);
            __syncthreads();
        }
    }

    // ---- epilogue: act + bias, direct float2 stores ----
    const int qr = lane >> 2;          // 0..7
    const int qc = (lane & 3) * 2;     // 0,2,4,6
#pragma unroll
    for (int mi = 0; mi < 2; mi++) {
#pragma unroll
        for (int ti = 0; ti < 8; ti++) {
            const int col = n0 + wn * 64 + ti * 8 + qc;
            float bcol0 = 0.f, bcol1 = 0.f;
            if (ACT != 0) { bcol0 = bias[col]; bcol1 = bias[col + 1]; }
#pragma unroll
            for (int rh = 0; rh < 2; rh++) {
                const int row = m0 + wm * 32 + mi * 16 + rh * 8 + qr;
                float x0 = acc[mi][ti][2 * rh + 0];
                float x1 = acc[mi][ti][2 * rh + 1];
                if (ACT == 1)      { x0 = expf(x0 + bcol0); x1 = expf(x1 + bcol1); }
                else if (ACT == 2) { x0 = 1.0f / (1.0f + expf(-(x0 + bcol0)));
                                     x1 = 1.0f / (1.0f + expf(-(x1 + bcol1))); }
                float2 vo = make_float2(x0, x1);
                *(float2*)&C[(size_t)row * ldc + col] = vo;
            }
        }
    }
}

// ---------------------------------------------------------------------------
// RMSNorm over head_dim=64, one warp per (row, head). In place.
// ---------------------------------------------------------------------------
__global__ void rmsnorm_k(float* __restrict__ x, const float* __restrict__ w, int nrows)
{
    int warp = (blockIdx.x * blockDim.x + threadIdx.x) >> 5;
    int lane = threadIdx.x & 31;
    if (warp >= nrows) return;
    float* p = x + (size_t)warp * 64;
    float a = p[lane], b = p[lane + 32];
    float ss = a * a + b * b;
#pragma unroll
    for (int o = 16; o; o >>= 1) ss += __shfl_xor_sync(0xffffffffu, ss, o);
    float s = rsqrtf(ss * (1.0f / 64.0f) + 1e-6f);
    p[lane]      = a * s * w[lane];
    p[lane + 32] = b * s * w[lane + 32];
}

// ---------------------------------------------------------------------------
// Sequential mLSTM scan (Round-5 target).
// ---------------------------------------------------------------------------
__device__ __forceinline__ void cp16(uint32_t s, const void* g)
{
    asm volatile("cp.async.ca.shared.global [%0], [%1], 16;\n" :: "r"(s), "l"(g));
}

__global__ void __launch_bounds__(128, 1)
mlstm_scan(const float* __restrict__ q, const float* __restrict__ k,
           const float* __restrict__ v, const float* __restrict__ ig,
           const float* __restrict__ fg, const float* __restrict__ og,
           const float* __restrict__ xp,
           float* __restrict__ hout)
{
    __shared__ float stage[2][7][64];
    __shared__ float red[4][64];
    __shared__ float denp[2];

    const int tid = threadIdx.x;
    const int b   = blockIdx.x >> 4;
    const int h   = blockIdx.x & 15;
    const size_t base  = ((size_t)b * LL) * 1024 + (size_t)h * 64;
    const size_t baseg = ((size_t)b * LL) * 2048 + 1024 + (size_t)h * 64;

    const float* srcs[8] = { q + base, k + base, v + base, ig + base,
                             fg + base, og + base, xp + baseg, q + base };

    const int  arr    = tid >> 4;
    const int  ch     = tid & 15;
    const bool loader = (tid < 112);
    const float* mySrc    = srcs[arr] + ch * 4;
    const size_t mystride = (arr == 6) ? 2048 : 1024;
    const uint32_t mydst0 = (uint32_t)__cvta_generic_to_shared(&stage[0][0][0]) + (arr * 64 + ch * 4) * 4;
    const uint32_t mydst1 = mydst0 + 7 * 64 * 4;

    if (loader) cp16(mydst0, mySrc);
    asm volatile("cp.async.commit_group;\n");

    const int r = tid >> 5;
    const int c = tid & 31;
    float C0[16], C1[16];
#pragma unroll
    for (int i = 0; i < 16; i++) { C0[i] = 0.0f; C1[i] = 0.0f; }
    float nreg = 0.0f;

    float* outp = hout + base;

    for (int t = 0; t < LL; t++) {
        asm volatile("cp.async.wait_group 0;\n" ::: "memory");
        __syncthreads();
        const int cur = t & 1;

        if (t + 1 < LL && loader)
            cp16(cur ? mydst0 : mydst1, mySrc + (size_t)(t + 1) * mystride);
        asm volatile("cp.async.commit_group;\n");

        const float* S   = &stage[cur][0][0];
        const float* qs  = S;
        const float* ks  = S + 64;
        const float* vs  = S + 128;
        const float* is_ = S + 192;
        const float* fs  = S + 256;
        const float* ogs = S + 320;
        const float* xgs = S + 384;

        float v0 = vs[c], v1 = vs[c + 32];
        float pn0 = 0.0f, pn1 = 0.0f;

#define ROWOP(ff, qq, aa, idx) { float _a = (aa);                              \
        C0[idx] = fmaf((ff), C0[idx], _a * v0); pn0 = fmaf((qq), C0[idx], pn0);\
        C1[idx] = fmaf((ff), C1[idx], _a * v1); pn1 = fmaf((qq), C1[idx], pn1); }

#pragma unroll
        for (int dd = 0; dd < 16; dd += 4) {
            int d = r * 16 + dd;
            float4 f4 = *(const float4*)&fs[d];
            float4 q4 = *(const float4*)&qs[d];
            float4 i4 = *(const float4*)&is_[d];
            float4 k4 = *(const float4*)&ks[d];
            ROWOP(f4.x, q4.x, i4.x * k4.x, dd + 0);
            ROWOP(f4.y, q4.y, i4.y * k4.y, dd + 1);
            ROWOP(f4.z, q4.z, i4.z * k4.z, dd + 2);
            ROWOP(f4.w, q4.w, i4.w * k4.w, dd + 3);
        }
#undef ROWOP

        red[r][c]      = pn0;
        red[r][c + 32] = pn1;

        if (tid < 64) {
            float a = is_[tid] * ks[tid];
            nreg = fmaf(fs[tid], nreg, a);
            float dp = qs[tid] * nreg;
#pragma unroll
            for (int o = 16; o; o >>= 1) dp += __shfl_xor_sync(0xffffffffu, dp, o);
            if ((tid & 31) == 0) denp[tid >> 5] = dp;
        }
        __syncthreads();

        if (tid < 64) {
            float num = red[0][tid] + red[1][tid] + red[2][tid] + red[3][tid];
            float den = fmaxf(denp[0] + denp[1], 1.0f);
            float ov  = (num / den) * ogs[tid] * (1.0f / (1.0f + expf(-xgs[tid])));
            outp[(size_t)t * 1024 + tid] = ov;
        }
    }
}

// ---------------------------------------------------------------------------
// Launch
// ---------------------------------------------------------------------------
extern "C" void kernel_launch(void* const* d_in, const int* in_sizes, int n_in,
                              void* d_out, int out_size)
{
    const float* x     = (const float*)d_in[0];
    const float* w_in  = (const float*)d_in[1];
    const float* w_q   = (const float*)d_in[2];
    const float* w_k   = (const float*)d_in[3];
    const float* w_v   = (const float*)d_in[4];
    const float* w_i   = (const float*)d_in[5];
    const float* b_i   = (const float*)d_in[6];
    const float* w_f   = (const float*)d_in[7];
    const float* b_f   = (const float*)d_in[8];
    const float* w_o   = (const float*)d_in[9];
    const float* b_o   = (const float*)d_in[10];
    const float* w_qn  = (const float*)d_in[11];
    const float* w_kn  = (const float*)d_in[12];
    const float* w_out = (const float*)d_in[13];
    float* out = (float*)d_out;

    float *xp, *qb, *kb, *vb, *ib, *fb, *ob, *hb;
    cudaGetSymbolAddress((void**)&xp, g_xp);
    cudaGetSymbolAddress((void**)&qb, g_q);
    cudaGetSymbolAddress((void**)&kb, g_k);
    cudaGetSymbolAddress((void**)&vb, g_v);
    cudaGetSymbolAddress((void**)&ib, g_i);
    cudaGetSymbolAddress((void**)&fb, g_f);
    cudaGetSymbolAddress((void**)&ob, g_o);
    cudaGetSymbolAddress((void**)&hb, g_h);

    cudaFuncSetAttribute(gemm_mma<0>, cudaFuncAttributeMaxDynamicSharedMemorySize, GEMM_SMEM);
    cudaFuncSetAttribute(gemm_mma<1>, cudaFuncAttributeMaxDynamicSharedMemorySize, GEMM_SMEM);
    cudaFuncSetAttribute(gemm_mma<2>, cudaFuncAttributeMaxDynamicSharedMemorySize, GEMM_SMEM);

    dim3 blk(256);
    dim3 gIn(2048 / 128, MROWS / 128);
    dim3 gSq(1024 / 128, MROWS / 128);

    gemm_mma<0><<<gIn, blk, GEMM_SMEM>>>(x, DIMD, w_in, nullptr, xp, 2048);

    gemm_mma<0><<<gSq, blk, GEMM_SMEM>>>(xp, 2048, w_q, nullptr, qb, 1024);
    gemm_mma<0><<<gSq, blk, GEMM_SMEM>>>(xp, 2048, w_k, nullptr, kb, 1024);
    gemm_mma<0><<<gSq, blk, GEMM_SMEM>>>(xp, 2048, w_v, nullptr, vb, 1024);
    gemm_mma<1><<<gSq, blk, GEMM_SMEM>>>(xp, 2048, w_i, b_i,    ib, 1024);
    gemm_mma<2><<<gSq, blk, GEMM_SMEM>>>(xp, 2048, w_f, b_f,    fb, 1024);
    gemm_mma<2><<<gSq, blk, GEMM_SMEM>>>(xp, 2048, w_o, b_o,    ob, 1024);

    const int headrows = MROWS * NH;
    rmsnorm_k<<<headrows / 8, 256>>>(qb, w_qn, headrows);
    rmsnorm_k<<<headrows / 8, 256>>>(kb, w_kn, headrows);

    mlstm_scan<<<BB * NH, 128>>>(qb, kb, vb, ib, fb, ob, xp, hb);

    gemm_mma<0><<<gSq, blk, GEMM_SMEM>>>(hb, 1024, w_out, nullptr, out, 1024);
}

// round 5
// speedup vs baseline: 2.8444x; 1.8987x over previous
#include <cuda_runtime.h>
#include <cuda_bf16.h>
#include <math.h>
#include <stdint.h>

// Problem constants
#define BB   2
#define LL   4096
#define DIMD 1024
#define NH   16
#define HD   64
#define MROWS (BB * LL)          // 8192
#define KDIM 1024
#define CHUNK  64
#define NCHUNK (LL / CHUNK)      // 64
#define NCID   (BB * NH * NCHUNK) // 2048

// ---------------------------------------------------------------------------
// Scratch
// ---------------------------------------------------------------------------
__device__ float g_xp[(size_t)MROWS * 2048];
__device__ float g_q [(size_t)MROWS * 1024];
__device__ float g_k [(size_t)MROWS * 1024];
__device__ float g_v [(size_t)MROWS * 1024];
__device__ float g_i [(size_t)MROWS * 1024];
__device__ float g_f [(size_t)MROWS * 1024];
__device__ float g_o [(size_t)MROWS * 1024];
__device__ float g_h [(size_t)MROWS * 1024];
// chunked-scan scratch
__device__ float g_dC [(size_t)NCID * 4096];   // per-chunk delta state
__device__ float g_dN [(size_t)NCID * 64];
__device__ float g_G  [(size_t)NCID * 64];
__device__ float g_Cst[(size_t)NCID * 4096];   // chunk-start states
__device__ float g_Nst[(size_t)NCID * 64];

// ---------------------------------------------------------------------------
// mma.sync split-bf16 GEMM (unchanged from R4)
// ---------------------------------------------------------------------------
#define BK 32
#define ROWB 80
#define SEC  10240
#define STAGE_BYTES (4 * SEC)
#define GEMM_SMEM (2 * STAGE_BYTES)

#define LDSM_X4(r0, r1, r2, r3, addr) \
    asm volatile("ldmatrix.sync.aligned.m8n8.x4.shared.b16 {%0,%1,%2,%3}, [%4];" \
                 : "=r"(r0), "=r"(r1), "=r"(r2), "=r"(r3) : "r"(addr))

#define MMA_BF16(d, a, b0, b1) \
    asm volatile("mma.sync.aligned.m16n8k16.row.col.f32.bf16.bf16.f32 " \
                 "{%0,%1,%2,%3}, {%4,%5,%6,%7}, {%8,%9}, {%0,%1,%2,%3};" \
                 : "+f"((d)[0]), "+f"((d)[1]), "+f"((d)[2]), "+f"((d)[3]) \
                 : "r"((a)[0]), "r"((a)[1]), "r"((a)[2]), "r"((a)[3]), \
                   "r"(b0), "r"(b1))

__device__ __forceinline__ uint32_t packbf(float x, float y) {
    __nv_bfloat16 bx = __float2bfloat16_rn(x);
    __nv_bfloat16 by = __float2bfloat16_rn(y);
    return (uint32_t)__bfloat16_as_ushort(bx) | ((uint32_t)__bfloat16_as_ushort(by) << 16);
}
__device__ __forceinline__ uint32_t packlo(float x, float y) {
    __nv_bfloat16 bx = __float2bfloat16_rn(x);
    __nv_bfloat16 by = __float2bfloat16_rn(y);
    float rx = x - __bfloat162float(bx);
    float ry = y - __bfloat162float(by);
    return packbf(rx, ry);
}
__device__ __forceinline__ void sts64(uint32_t a, uint32_t v0, uint32_t v1) {
    asm volatile("st.shared.v2.b32 [%0], {%1, %2};" :: "r"(a), "r"(v0), "r"(v1) : "memory");
}

template <int ACT>
__global__ void __launch_bounds__(256, 1)
gemm_mma(const float* __restrict__ A, int lda,
         const float* __restrict__ B,
         const float* __restrict__ bias,
         float* __restrict__ C, int ldc)
{
    extern __shared__ __align__(128) char smem[];
    const uint32_t sbase = (uint32_t)__cvta_generic_to_shared(smem);

    const int tid  = threadIdx.x;
    const int w    = tid >> 5;
    const int lane = tid & 31;
    const int wm   = w & 3;
    const int wn   = w >> 2;

    const int m0 = blockIdx.y * 128;
    const int n0 = blockIdx.x * 128;

    const int arow = tid >> 1;
    const int ak   = (tid & 1) << 4;
    const float* Ag = A + (size_t)(m0 + arow) * lda + ak;
    const float* Bg = B + (size_t)(n0 + arow) * KDIM + ak;
    const uint32_t sA = sbase + (uint32_t)(arow * ROWB + ak * 2);
    const uint32_t sB = sA + 2 * SEC;

    float4 ra[4], rb[4];
    auto LDG = [&](int k0) {
#pragma unroll
        for (int i = 0; i < 4; i++) {
            ra[i] = *(const float4*)(Ag + k0 + 4 * i);
            rb[i] = *(const float4*)(Bg + k0 + 4 * i);
        }
    };
    auto STS = [&](int buf) {
        const uint32_t bo = (uint32_t)(buf * STAGE_BYTES);
#pragma unroll
        for (int i = 0; i < 4; i++) {
            sts64(sA + bo + 8 * i,       packbf(ra[i].x, ra[i].y), packbf(ra[i].z, ra[i].w));
            sts64(sA + bo + SEC + 8 * i, packlo(ra[i].x, ra[i].y), packlo(ra[i].z, ra[i].w));
            sts64(sB + bo + 8 * i,       packbf(rb[i].x, rb[i].y), packbf(rb[i].z, rb[i].w));
            sts64(sB + bo + SEC + 8 * i, packlo(rb[i].x, rb[i].y), packlo(rb[i].z, rb[i].w));
        }
    };

    const int a_r = (lane & 7) + ((lane >> 3) & 1) * 8;
    const int a_k = ((lane >> 4) & 1) * 8;
    const int g   = lane >> 3;
    const int b_r = ((g >> 1) * 8) + (lane & 7);
    const int b_k = (g & 1) * 8;

    const uint32_t aAddr0 = sbase + (uint32_t)((wm * 32 + a_r) * ROWB + a_k * 2);
    const uint32_t bAddr0 = sbase + 2 * SEC + (uint32_t)((wn * 64 + b_r) * ROWB + b_k * 2);

    float acc[2][8][4] = {};

    LDG(0);
    STS(0);
    __syncthreads();

    const int S = KDIM / BK;
    for (int s = 0; s < S; s++) {
        if (s + 1 < S) LDG((s + 1) * BK);
        const uint32_t bo = (uint32_t)((s & 1) * STAGE_BYTES);

#pragma unroll
        for (int kb = 0; kb < 2; kb++) {
            const uint32_t ko = (uint32_t)(kb * 32);
            uint32_t Ah[2][4], Al[2][4], Bh[4][4], Bl[4][4];
#pragma unroll
            for (int mi = 0; mi < 2; mi++) {
                uint32_t aa = aAddr0 + bo + ko + (uint32_t)(mi * 16 * ROWB);
                LDSM_X4(Ah[mi][0], Ah[mi][1], Ah[mi][2], Ah[mi][3], aa);
                LDSM_X4(Al[mi][0], Al[mi][1], Al[mi][2], Al[mi][3], aa + SEC);
            }
#pragma unroll
            for (int gi = 0; gi < 4; gi++) {
                uint32_t ba = bAddr0 + bo + ko + (uint32_t)(gi * 16 * ROWB);
                LDSM_X4(Bh[gi][0], Bh[gi][1], Bh[gi][2], Bh[gi][3], ba);
                LDSM_X4(Bl[gi][0], Bl[gi][1], Bl[gi][2], Bl[gi][3], ba + SEC);
            }
#pragma unroll
            for (int mi = 0; mi < 2; mi++)
#pragma unroll
                for (int gi = 0; gi < 4; gi++)
#pragma unroll
                    for (int hf = 0; hf < 2; hf++) {
                        float* d = acc[mi][gi * 2 + hf];
                        MMA_BF16(d, Ah[mi], Bh[gi][2 * hf], Bh[gi][2 * hf + 1]);
                        MMA_BF16(d, Ah[mi], Bl[gi][2 * hf], Bl[gi][2 * hf + 1]);
                        MMA_BF16(d, Al[mi], Bh[gi][2 * hf], Bh[gi][2 * hf + 1]);
                    }
        }

        if (s + 1 < S) {
            STS((s + 1) & 1);
            __syncthreads();
        }
    }

    const int qr = lane >> 2;
    const int qc = (lane & 3) * 2;
#pragma unroll
    for (int mi = 0; mi < 2; mi++) {
#pragma unroll
        for (int ti = 0; ti < 8; ti++) {
            const int col = n0 + wn * 64 + ti * 8 + qc;
            float bcol0 = 0.f, bcol1 = 0.f;
            if (ACT != 0) { bcol0 = bias[col]; bcol1 = bias[col + 1]; }
#pragma unroll
            for (int rh = 0; rh < 2; rh++) {
                const int row = m0 + wm * 32 + mi * 16 + rh * 8 + qr;
                float x0 = acc[mi][ti][2 * rh + 0];
                float x1 = acc[mi][ti][2 * rh + 1];
                if (ACT == 1)      { x0 = expf(x0 + bcol0); x1 = expf(x1 + bcol1); }
                else if (ACT == 2) { x0 = 1.0f / (1.0f + expf(-(x0 + bcol0)));
                                     x1 = 1.0f / (1.0f + expf(-(x1 + bcol1))); }
                float2 vo = make_float2(x0, x1);
                *(float2*)&C[(size_t)row * ldc + col] = vo;
            }
        }
    }
}

// ---------------------------------------------------------------------------
// RMSNorm over head_dim=64, one warp per (row, head). In place.
// ---------------------------------------------------------------------------
__global__ void rmsnorm_k(float* __restrict__ x, const float* __restrict__ w, int nrows)
{
    int warp = (blockIdx.x * blockDim.x + threadIdx.x) >> 5;
    int lane = threadIdx.x & 31;
    if (warp >= nrows) return;
    float* p = x + (size_t)warp * 64;
    float a = p[lane], b = p[lane + 32];
    float ss = a * a + b * b;
#pragma unroll
    for (int o = 16; o; o >>= 1) ss += __shfl_xor_sync(0xffffffffu, ss, o);
    float s = rsqrtf(ss * (1.0f / 64.0f) + 1e-6f);
    p[lane]      = a * s * w[lane];
    p[lane + 32] = b * s * w[lane + 32];
}

// ---------------------------------------------------------------------------
// Chunk-parallel mLSTM scan.
// Thread layout (passes 1 and 3, 128 threads): warp r owns state rows
// d = 16r..16r+15; lane c owns columns c and c+32. Threads 0..63 own n[d].
// ---------------------------------------------------------------------------
__device__ __forceinline__ void cp16(uint32_t s, const void* g)
{
    asm volatile("cp.async.ca.shared.global [%0], [%1], 16;\n" :: "r"(s), "l"(g));
}

// -------- Pass 1: per-chunk forward recurrence from zero state -------------
__global__ void __launch_bounds__(128, 4)
chunk_fwd(const float* __restrict__ k, const float* __restrict__ v,
          const float* __restrict__ ig, const float* __restrict__ fg,
          float* __restrict__ dC, float* __restrict__ dN, float* __restrict__ G)
{
    __shared__ float stage[2][4][64];

    const int tid = threadIdx.x;
    const int cid = blockIdx.x;           // (bh, chunk)
    const int j   = cid & (NCHUNK - 1);
    const int bh  = cid >> 6;
    const int b   = bh >> 4;
    const int h   = bh & 15;
    const size_t base = ((size_t)b * LL + (size_t)j * CHUNK) * 1024 + (size_t)h * 64;

    const float* srcs[4] = { k + base, v + base, ig + base, fg + base };
    const int  arr = tid >> 4;            // 0..7, only 0..3 used
    const int  ch  = tid & 15;
    const bool loader = (tid < 64);
    const float* mySrc = srcs[loader ? arr : 0] + ch * 4;
    const uint32_t mydst0 = (uint32_t)__cvta_generic_to_shared(&stage[0][0][0]) + (arr * 64 + ch * 4) * 4;
    const uint32_t mydst1 = mydst0 + 4 * 64 * 4;

    if (loader) cp16(mydst0, mySrc);
    asm volatile("cp.async.commit_group;\n");

    const int r = tid >> 5;
    const int c = tid & 31;
    float C0[16], C1[16];
#pragma unroll
    for (int i = 0; i < 16; i++) { C0[i] = 0.0f; C1[i] = 0.0f; }
    float nreg = 0.0f, greg = 1.0f;

    for (int t = 0; t < CHUNK; t++) {
        asm volatile("cp.async.wait_group 0;\n" ::: "memory");
        __syncthreads();
        const int cur = t & 1;

        if (t + 1 < CHUNK && loader)
            cp16(cur ? mydst0 : mydst1, mySrc + (size_t)(t + 1) * 1024);
        asm volatile("cp.async.commit_group;\n");

        const float* S   = &stage[cur][0][0];
        const float* ks  = S;
        const float* vs  = S + 64;
        const float* is_ = S + 128;
        const float* fs  = S + 192;

        float v0 = vs[c], v1 = vs[c + 32];

#pragma unroll
        for (int dd = 0; dd < 16; dd += 4) {
            int d = r * 16 + dd;
            float4 f4 = *(const float4*)&fs[d];
            float4 i4 = *(const float4*)&is_[d];
            float4 k4 = *(const float4*)&ks[d];
            float a0 = i4.x * k4.x, a1 = i4.y * k4.y, a2 = i4.z * k4.z, a3 = i4.w * k4.w;
            C0[dd+0] = fmaf(f4.x, C0[dd+0], a0 * v0); C1[dd+0] = fmaf(f4.x, C1[dd+0], a0 * v1);
            C0[dd+1] = fmaf(f4.y, C0[dd+1], a1 * v0); C1[dd+1] = fmaf(f4.y, C1[dd+1], a1 * v1);
            C0[dd+2] = fmaf(f4.z, C0[dd+2], a2 * v0); C1[dd+2] = fmaf(f4.z, C1[dd+2], a2 * v1);
            C0[dd+3] = fmaf(f4.w, C0[dd+3], a3 * v0); C1[dd+3] = fmaf(f4.w, C1[dd+3], a3 * v1);
        }

        if (tid < 64) {
            float ft = fs[tid];
            nreg = fmaf(ft, nreg, is_[tid] * ks[tid]);
            greg *= ft;
        }
        __syncthreads();
    }

    // write outputs
    float* dCp = dC + (size_t)cid * 4096;
#pragma unroll
    for (int dd = 0; dd < 16; dd++) {
        dCp[(r * 16 + dd) * 64 + c]      = C0[dd];
        dCp[(r * 16 + dd) * 64 + c + 32] = C1[dd];
    }
    if (tid < 64) {
        dN[(size_t)cid * 64 + tid] = nreg;
        G [(size_t)cid * 64 + tid] = greg;
    }
}

// -------- Pass 2: sequential carry across chunks ---------------------------
__global__ void __launch_bounds__(128, 1)
chunk_carry(const float* __restrict__ dC, const float* __restrict__ dN,
            const float* __restrict__ G,
            float* __restrict__ Cst, float* __restrict__ Nst)
{
    __shared__ float gs[64], dns[64];
    const int tid = threadIdx.x;
    const int bh  = blockIdx.x;
    const int r = tid >> 5;
    const int c = tid & 31;

    float C0[16], C1[16];
#pragma unroll
    for (int i = 0; i < 16; i++) { C0[i] = 0.0f; C1[i] = 0.0f; }
    float n = 0.0f;

    for (int j = 0; j < NCHUNK; j++) {
        const size_t cid = (size_t)bh * NCHUNK + j;
        float* Cp = Cst + cid * 4096;
        const float* Dp = dC + cid * 4096;

        if (tid < 64) {
            Nst[cid * 64 + tid] = n;
            gs[tid]  = G [cid * 64 + tid];
            dns[tid] = dN[cid * 64 + tid];
        }
#pragma unroll
        for (int dd = 0; dd < 16; dd++) {
            Cp[(r * 16 + dd) * 64 + c]      = C0[dd];
            Cp[(r * 16 + dd) * 64 + c + 32] = C1[dd];
        }
        __syncthreads();
#pragma unroll
        for (int dd = 0; dd < 16; dd++) {
            float gd = gs[r * 16 + dd];
            C0[dd] = fmaf(gd, C0[dd], Dp[(r * 16 + dd) * 64 + c]);
            C1[dd] = fmaf(gd, C1[dd], Dp[(r * 16 + dd) * 64 + c + 32]);
        }
        if (tid < 64) n = fmaf(gs[tid], n, dns[tid]);
        __syncthreads();
    }
}

// -------- Pass 3: per-chunk replay with outputs ----------------------------
__global__ void __launch_bounds__(128, 4)
chunk_out(const float* __restrict__ q, const float* __restrict__ k,
          const float* __restrict__ v, const float* __restrict__ ig,
          const float* __restrict__ fg, const float* __restrict__ og,
          const float* __restrict__ xp,
          const float* __restrict__ Cst, const float* __restrict__ Nst,
          float* __restrict__ hout)
{
    __shared__ float stage[2][7][64];
    __shared__ float red[4][64];
    __shared__ float denp[2];

    const int tid = threadIdx.x;
    const int cid = blockIdx.x;
    const int j   = cid & (NCHUNK - 1);
    const int bh  = cid >> 6;
    const int b   = bh >> 4;
    const int h   = bh & 15;
    const size_t base  = ((size_t)b * LL + (size_t)j * CHUNK) * 1024 + (size_t)h * 64;
    const size_t baseg = ((size_t)b * LL + (size_t)j * CHUNK) * 2048 + 1024 + (size_t)h * 64;

    const float* srcs[8] = { q + base, k + base, v + base, ig + base,
                             fg + base, og + base, xp + baseg, q + base };

    const int  arr = tid >> 4;
    const int  ch  = tid & 15;
    const bool loader = (tid < 112);
    const float* mySrc    = srcs[arr] + ch * 4;
    const size_t mystride = (arr == 6) ? 2048 : 1024;
    const uint32_t mydst0 = (uint32_t)__cvta_generic_to_shared(&stage[0][0][0]) + (arr * 64 + ch * 4) * 4;
    const uint32_t mydst1 = mydst0 + 7 * 64 * 4;

    if (loader) cp16(mydst0, mySrc);
    asm volatile("cp.async.commit_group;\n");

    const int r = tid >> 5;
    const int c = tid & 31;

    // init state from chunk-start buffers
    const float* Cp = Cst + (size_t)cid * 4096;
    float C0[16], C1[16];
#pragma unroll
    for (int dd = 0; dd < 16; dd++) {
        C0[dd] = Cp[(r * 16 + dd) * 64 + c];
        C1[dd] = Cp[(r * 16 + dd) * 64 + c + 32];
    }
    float nreg = (tid < 64) ? Nst[(size_t)cid * 64 + tid] : 0.0f;

    float* outp = hout + base;

    for (int t = 0; t < CHUNK; t++) {
        asm volatile("cp.async.wait_group 0;\n" ::: "memory");
        __syncthreads();
        const int cur = t & 1;

        if (t + 1 < CHUNK && loader)
            cp16(cur ? mydst0 : mydst1, mySrc + (size_t)(t + 1) * mystride);
        asm volatile("cp.async.commit_group;\n");

        const float* S   = &stage[cur][0][0];
        const float* qs  = S;
        const float* ks  = S + 64;
        const float* vs  = S + 128;
        const float* is_ = S + 192;
        const float* fs  = S + 256;
        const float* ogs = S + 320;
        const float* xgs = S + 384;

        float v0 = vs[c], v1 = vs[c + 32];
        float pn0 = 0.0f, pn1 = 0.0f;

#define ROWOP(ff, qq, aa, idx) { float _a = (aa);                              \
        C0[idx] = fmaf((ff), C0[idx], _a * v0); pn0 = fmaf((qq), C0[idx], pn0);\
        C1[idx] = fmaf((ff), C1[idx], _a * v1); pn1 = fmaf((qq), C1[idx], pn1); }

#pragma unroll
        for (int dd = 0; dd < 16; dd += 4) {
            int d = r * 16 + dd;
            float4 f4 = *(const float4*)&fs[d];
            float4 q4 = *(const float4*)&qs[d];
            float4 i4 = *(const float4*)&is_[d];
            float4 k4 = *(const float4*)&ks[d];
            ROWOP(f4.x, q4.x, i4.x * k4.x, dd + 0);
            ROWOP(f4.y, q4.y, i4.y * k4.y, dd + 1);
            ROWOP(f4.z, q4.z, i4.z * k4.z, dd + 2);
            ROWOP(f4.w, q4.w, i4.w * k4.w, dd + 3);
        }
#undef ROWOP

        red[r][c]      = pn0;
        red[r][c + 32] = pn1;

        if (tid < 64) {
            float a = is_[tid] * ks[tid];
            nreg = fmaf(fs[tid], nreg, a);
            float dp = qs[tid] * nreg;
#pragma unroll
            for (int o = 16; o; o >>= 1) dp += __shfl_xor_sync(0xffffffffu, dp, o);
            if ((tid & 31) == 0) denp[tid >> 5] = dp;
        }
        __syncthreads();

        if (tid < 64) {
            float num = red[0][tid] + red[1][tid] + red[2][tid] + red[3][tid];
            float den = fmaxf(denp[0] + denp[1], 1.0f);
            float ov  = (num / den) * ogs[tid] * (1.0f / (1.0f + expf(-xgs[tid])));
            outp[(size_t)t * 1024 + tid] = ov;
        }
    }
}

// ---------------------------------------------------------------------------
// Launch
// ---------------------------------------------------------------------------
extern "C" void kernel_launch(void* const* d_in, const int* in_sizes, int n_in,
                              void* d_out, int out_size)
{
    const float* x     = (const float*)d_in[0];
    const float* w_in  = (const float*)d_in[1];
    const float* w_q   = (const float*)d_in[2];
    const float* w_k   = (const float*)d_in[3];
    const float* w_v   = (const float*)d_in[4];
    const float* w_i   = (const float*)d_in[5];
    const float* b_i   = (const float*)d_in[6];
    const float* w_f   = (const float*)d_in[7];
    const float* b_f   = (const float*)d_in[8];
    const float* w_o   = (const float*)d_in[9];
    const float* b_o   = (const float*)d_in[10];
    const float* w_qn  = (const float*)d_in[11];
    const float* w_kn  = (const float*)d_in[12];
    const float* w_out = (const float*)d_in[13];
    float* out = (float*)d_out;

    float *xp, *qb, *kb, *vb, *ib, *fb, *ob, *hb;
    float *dC, *dN, *G, *Cst, *Nst;
    cudaGetSymbolAddress((void**)&xp, g_xp);
    cudaGetSymbolAddress((void**)&qb, g_q);
    cudaGetSymbolAddress((void**)&kb, g_k);
    cudaGetSymbolAddress((void**)&vb, g_v);
    cudaGetSymbolAddress((void**)&ib, g_i);
    cudaGetSymbolAddress((void**)&fb, g_f);
    cudaGetSymbolAddress((void**)&ob, g_o);
    cudaGetSymbolAddress((void**)&hb, g_h);
    cudaGetSymbolAddress((void**)&dC, g_dC);
    cudaGetSymbolAddress((void**)&dN, g_dN);
    cudaGetSymbolAddress((void**)&G,  g_G);
    cudaGetSymbolAddress((void**)&Cst, g_Cst);
    cudaGetSymbolAddress((void**)&Nst, g_Nst);

    cudaFuncSetAttribute(gemm_mma<0>, cudaFuncAttributeMaxDynamicSharedMemorySize, GEMM_SMEM);
    cudaFuncSetAttribute(gemm_mma<1>, cudaFuncAttributeMaxDynamicSharedMemorySize, GEMM_SMEM);
    cudaFuncSetAttribute(gemm_mma<2>, cudaFuncAttributeMaxDynamicSharedMemorySize, GEMM_SMEM);

    dim3 blk(256);
    dim3 gIn(2048 / 128, MROWS / 128);
    dim3 gSq(1024 / 128, MROWS / 128);

    gemm_mma<0><<<gIn, blk, GEMM_SMEM>>>(x, DIMD, w_in, nullptr, xp, 2048);

    gemm_mma<0><<<gSq, blk, GEMM_SMEM>>>(xp, 2048, w_q, nullptr, qb, 1024);
    gemm_mma<0><<<gSq, blk, GEMM_SMEM>>>(xp, 2048, w_k, nullptr, kb, 1024);
    gemm_mma<0><<<gSq, blk, GEMM_SMEM>>>(xp, 2048, w_v, nullptr, vb, 1024);
    gemm_mma<1><<<gSq, blk, GEMM_SMEM>>>(xp, 2048, w_i, b_i,    ib, 1024);
    gemm_mma<2><<<gSq, blk, GEMM_SMEM>>>(xp, 2048, w_f, b_f,    fb, 1024);
    gemm_mma<2><<<gSq, blk, GEMM_SMEM>>>(xp, 2048, w_o, b_o,    ob, 1024);

    const int headrows = MROWS * NH;
    rmsnorm_k<<<headrows / 8, 256>>>(qb, w_qn, headrows);
    rmsnorm_k<<<headrows / 8, 256>>>(kb, w_kn, headrows);

    // chunk-parallel scan
    chunk_fwd  <<<NCID, 128>>>(kb, vb, ib, fb, dC, dN, G);
    chunk_carry<<<BB * NH, 128>>>(dC, dN, G, Cst, Nst);
    chunk_out  <<<NCID, 128>>>(qb, kb, vb, ib, fb, ob, xp, Cst, Nst, hb);

    gemm_mma<0><<<gSq, blk, GEMM_SMEM>>>(hb, 1024, w_out, nullptr, out, 1024);
}

// round 6
// speedup vs baseline: 3.4809x; 1.2238x over previous
#include <cuda_runtime.h>
#include <cuda_bf16.h>
#include <math.h>
#include <stdint.h>

// Problem constants
#define BB   2
#define LL   4096
#define DIMD 1024
#define NH   16
#define HD   64
#define MROWS (BB * LL)          // 8192
#define KDIM 1024
#define CHUNK  64
#define NCHUNK (LL / CHUNK)      // 64
#define NCID   (BB * NH * NCHUNK) // 2048

// ---------------------------------------------------------------------------
// Scratch
// ---------------------------------------------------------------------------
__device__ float g_xp[(size_t)MROWS * 2048];
__device__ float g_q [(size_t)MROWS * 1024];
__device__ float g_k [(size_t)MROWS * 1024];
__device__ float g_v [(size_t)MROWS * 1024];
__device__ float g_i [(size_t)MROWS * 1024];
__device__ float g_f [(size_t)MROWS * 1024];
__device__ float g_o [(size_t)MROWS * 1024];
// bf16 split operand buffers
__device__ __nv_bfloat16 g_xh [(size_t)MROWS * 1024];
__device__ __nv_bfloat16 g_xl [(size_t)MROWS * 1024];
__device__ __nv_bfloat16 g_xph[(size_t)MROWS * 2048];
__device__ __nv_bfloat16 g_xpl[(size_t)MROWS * 2048];
__device__ __nv_bfloat16 g_hh [(size_t)MROWS * 1024];
__device__ __nv_bfloat16 g_hl [(size_t)MROWS * 1024];
__device__ __nv_bfloat16 g_wih[(size_t)2048 * 1024];
__device__ __nv_bfloat16 g_wil[(size_t)2048 * 1024];
__device__ __nv_bfloat16 g_w6h[(size_t)6 * 1024 * 1024];
__device__ __nv_bfloat16 g_w6l[(size_t)6 * 1024 * 1024];
__device__ __nv_bfloat16 g_woh[(size_t)1024 * 1024];
__device__ __nv_bfloat16 g_wol[(size_t)1024 * 1024];
// chunked-scan scratch
__device__ float g_dC [(size_t)NCID * 4096];
__device__ float g_dN [(size_t)NCID * 64];
__device__ float g_G  [(size_t)NCID * 64];
__device__ float g_Cst[(size_t)NCID * 4096];
__device__ float g_Nst[(size_t)NCID * 64];

// ---------------------------------------------------------------------------
// helpers
// ---------------------------------------------------------------------------
__device__ __forceinline__ uint32_t packbf(float x, float y) {
    __nv_bfloat16 bx = __float2bfloat16_rn(x);
    __nv_bfloat16 by = __float2bfloat16_rn(y);
    return (uint32_t)__bfloat16_as_ushort(bx) | ((uint32_t)__bfloat16_as_ushort(by) << 16);
}
__device__ __forceinline__ uint32_t packlo(float x, float y) {
    __nv_bfloat16 bx = __float2bfloat16_rn(x);
    __nv_bfloat16 by = __float2bfloat16_rn(y);
    return packbf(x - __bfloat162float(bx), y - __bfloat162float(by));
}
__device__ __forceinline__ void cp16(uint32_t s, const void* g)
{
    asm volatile("cp.async.ca.shared.global [%0], [%1], 16;\n" :: "r"(s), "l"(g));
}

#define LDSM_X4(r0, r1, r2, r3, addr) \
    asm volatile("ldmatrix.sync.aligned.m8n8.x4.shared.b16 {%0,%1,%2,%3}, [%4];" \
                 : "=r"(r0), "=r"(r1), "=r"(r2), "=r"(r3) : "r"(addr))

#define MMA_BF16(d, a, b0, b1) \
    asm volatile("mma.sync.aligned.m16n8k16.row.col.f32.bf16.bf16.f32 " \
                 "{%0,%1,%2,%3}, {%4,%5,%6,%7}, {%8,%9}, {%0,%1,%2,%3};" \
                 : "+f"((d)[0]), "+f"((d)[1]), "+f"((d)[2]), "+f"((d)[3]) \
                 : "r"((a)[0]), "r"((a)[1]), "r"((a)[2]), "r"((a)[3]), \
                   "r"(b0), "r"(b1))

// ---------------------------------------------------------------------------
// Pass 0: fp32 -> (hi, lo) bf16 split, vectorized
// ---------------------------------------------------------------------------
__global__ void split_k(const float4* __restrict__ s, uint2* __restrict__ hi,
                        uint2* __restrict__ lo, int n4)
{
    int i = blockIdx.x * 256 + threadIdx.x;
    if (i >= n4) return;
    float4 v = s[i];
    uint2 h, l;
    h.x = packbf(v.x, v.y); h.y = packbf(v.z, v.w);
    l.x = packlo(v.x, v.y); l.y = packlo(v.z, v.w);
    hi[i] = h; lo[i] = l;
}

// ---------------------------------------------------------------------------
// cp.async pipelined split-bf16 GEMM.
// C[M,N] = (Ah+Al)[M,K] @ (Bh+Bl)[N,K]^T (3-term), K=1024, CTA 128x128, BK=32.
// smem/stage: Ah|Al|Bh|Bl, each 128 rows x 64B (SW64 swizzled) = 32KB; 4 stages.
// ACT: 0 none, 1 exp(+bias), 2 sigmoid(+bias), 3 rmsnorm(head=64, w=bias)
// SPLIT: also emit bf16 hi/lo of output.
// ---------------------------------------------------------------------------
#define STAGES 4
#define SECB   8192
#define STAGEB 32768
#define GEMM_SMEM (STAGES * STAGEB)   // 131072

template <int ACT, int SPLIT>
__global__ void __launch_bounds__(256, 1)
gemm_bf(const __nv_bfloat16* __restrict__ Ah, const __nv_bfloat16* __restrict__ Al, int lda,
        const __nv_bfloat16* __restrict__ Bh, const __nv_bfloat16* __restrict__ Bl,
        const float* __restrict__ bias,
        float* __restrict__ C, int ldc,
        __nv_bfloat16* __restrict__ Chh, __nv_bfloat16* __restrict__ Cll)
{
    extern __shared__ __align__(128) char smem[];
    const uint32_t sbase = (uint32_t)__cvta_generic_to_shared(smem);

    const int tid  = threadIdx.x;
    const int w    = tid >> 5;
    const int lane = tid & 31;
    const int wm   = w & 3;
    const int wn   = w >> 2;

    const int m0 = blockIdx.y * 128;
    const int n0 = blockIdx.x * 128;

    const __nv_bfloat16* Ahp = Ah + (size_t)m0 * lda;
    const __nv_bfloat16* Alp = Al + (size_t)m0 * lda;
    const __nv_bfloat16* Bhp = Bh + (size_t)n0 * KDIM;
    const __nv_bfloat16* Blp = Bl + (size_t)n0 * KDIM;

    // loader: 2048 16B chunks / stage, 8 per thread
    auto load_stage = [&](int st, int k0) {
        const uint32_t db = sbase + (uint32_t)((st & (STAGES - 1)) * STAGEB);
#pragma unroll
        for (int i = 0; i < 8; i++) {
            const int ci  = tid + i * 256;
            const int sec = ci >> 9;
            const int r   = (ci >> 2) & 127;
            const int kq  = ci & 3;
            const __nv_bfloat16* gp;
            if      (sec == 0) gp = Ahp + (size_t)r * lda;
            else if (sec == 1) gp = Alp + (size_t)r * lda;
            else if (sec == 2) gp = Bhp + (size_t)r * KDIM;
            else               gp = Blp + (size_t)r * KDIM;
            gp += k0 + kq * 8;
            const uint32_t d = db + (uint32_t)(sec * SECB + r * 64 + ((kq * 16) ^ ((r * 8) & 0x30)));
            cp16(d, gp);
        }
    };

    // ldmatrix per-lane addressing (SW64 rows: 64B, XOR bits[5:4] with row bits[2:1])
    const int a_r  = (lane & 7) + ((lane >> 3) & 1) * 8;
    const int ak2  = ((lane >> 4) & 1) * 16;
    const uint32_t axr = (uint32_t)((a_r << 3) & 0x30);
    const int g    = lane >> 3;
    const int b_r  = ((g >> 1) * 8) + (lane & 7);
    const int bk2  = (g & 1) * 16;
    const uint32_t bxr = (uint32_t)((b_r << 3) & 0x30);

    uint32_t aoff[2], boff[4];
#pragma unroll
    for (int mi = 0; mi < 2; mi++) aoff[mi] = (uint32_t)((wm * 32 + mi * 16 + a_r) * 64);
#pragma unroll
    for (int gi = 0; gi < 4; gi++) boff[gi] = (uint32_t)(2 * SECB + (wn * 64 + gi * 16 + b_r) * 64);

    float acc[2][8][4] = {};

    for (int st = 0; st < 3; st++) {
        load_stage(st, st * 32);
        asm volatile("cp.async.commit_group;\n");
    }

    const int S = KDIM / 32;   // 32
    for (int s = 0; s < S; s++) {
        asm volatile("cp.async.wait_group 2;\n" ::: "memory");
        __syncthreads();
        if (s + 3 < S) load_stage(s + 3, (s + 3) * 32);
        asm volatile("cp.async.commit_group;\n");

        const uint32_t bb = sbase + (uint32_t)((s & (STAGES - 1)) * STAGEB);
#pragma unroll
        for (int kb = 0; kb < 2; kb++) {
            uint32_t Ahf[2][4], Alf[2][4], Bhf[4][4], Blf[4][4];
#pragma unroll
            for (int mi = 0; mi < 2; mi++) {
                const uint32_t aa = bb + aoff[mi] + (uint32_t)((kb * 32 + ak2) ^ axr);
                LDSM_X4(Ahf[mi][0], Ahf[mi][1], Ahf[mi][2], Ahf[mi][3], aa);
                LDSM_X4(Alf[mi][0], Alf[mi][1], Alf[mi][2], Alf[mi][3], aa + SECB);
            }
#pragma unroll
            for (int gi = 0; gi < 4; gi++) {
                const uint32_t ba = bb + boff[gi] + (uint32_t)((kb * 32 + bk2) ^ bxr);
                LDSM_X4(Bhf[gi][0], Bhf[gi][1], Bhf[gi][2], Bhf[gi][3], ba);
                LDSM_X4(Blf[gi][0], Blf[gi][1], Blf[gi][2], Blf[gi][3], ba + SECB);
            }
#pragma unroll
            for (int mi = 0; mi < 2; mi++)
#pragma unroll
                for (int gi = 0; gi < 4; gi++)
#pragma unroll
                    for (int hf = 0; hf < 2; hf++) {
                        float* d = acc[mi][gi * 2 + hf];
                        MMA_BF16(d, Ahf[mi], Bhf[gi][2 * hf], Bhf[gi][2 * hf + 1]);
                        MMA_BF16(d, Ahf[mi], Blf[gi][2 * hf], Blf[gi][2 * hf + 1]);
                        MMA_BF16(d, Alf[mi], Bhf[gi][2 * hf], Bhf[gi][2 * hf + 1]);
                    }
        }
    }

    const int qr = lane >> 2;
    const int qc = (lane & 3) * 2;

    // fused per-head RMSNorm: each warp column group = one 64-dim head
    if (ACT == 3) {
#pragma unroll
        for (int mi = 0; mi < 2; mi++)
#pragma unroll
            for (int rh = 0; rh < 2; rh++) {
                float ss = 0.0f;
#pragma unroll
                for (int ti = 0; ti < 8; ti++) {
                    float a = acc[mi][ti][2 * rh], b2 = acc[mi][ti][2 * rh + 1];
                    ss += a * a + b2 * b2;
                }
                ss += __shfl_xor_sync(0xffffffffu, ss, 1);
                ss += __shfl_xor_sync(0xffffffffu, ss, 2);
                const float sc = rsqrtf(ss * (1.0f / 64.0f) + 1e-6f);
#pragma unroll
                for (int ti = 0; ti < 8; ti++) {
                    acc[mi][ti][2 * rh]     *= sc * bias[ti * 8 + qc];
                    acc[mi][ti][2 * rh + 1] *= sc * bias[ti * 8 + qc + 1];
                }
            }
    }

#pragma unroll
    for (int mi = 0; mi < 2; mi++) {
#pragma unroll
        for (int ti = 0; ti < 8; ti++) {
            const int col = n0 + wn * 64 + ti * 8 + qc;
            float bcol0 = 0.f, bcol1 = 0.f;
            if (ACT == 1 || ACT == 2) { bcol0 = bias[col]; bcol1 = bias[col + 1]; }
#pragma unroll
            for (int rh = 0; rh < 2; rh++) {
                const int row = m0 + wm * 32 + mi * 16 + rh * 8 + qr;
                float x0 = acc[mi][ti][2 * rh + 0];
                float x1 = acc[mi][ti][2 * rh + 1];
                if (ACT == 1)      { x0 = expf(x0 + bcol0); x1 = expf(x1 + bcol1); }
                else if (ACT == 2) { x0 = 1.0f / (1.0f + expf(-(x0 + bcol0)));
                                     x1 = 1.0f / (1.0f + expf(-(x1 + bcol1))); }
                *(float2*)&C[(size_t)row * ldc + col] = make_float2(x0, x1);
                if (SPLIT) {
                    *(uint32_t*)&Chh[(size_t)row * ldc + col] = packbf(x0, x1);
                    *(uint32_t*)&Cll[(size_t)row * ldc + col] = packlo(x0, x1);
                }
            }
        }
    }
}

// ---------------------------------------------------------------------------
// Chunk-parallel mLSTM scan (pass1/carry unchanged from R5; pass3 emits split h)
// ---------------------------------------------------------------------------
__global__ void __launch_bounds__(128, 4)
chunk_fwd(const float* __restrict__ k, const float* __restrict__ v,
          const float* __restrict__ ig, const float* __restrict__ fg,
          float* __restrict__ dC, float* __restrict__ dN, float* __restrict__ G)
{
    __shared__ float stage[2][4][64];

    const int tid = threadIdx.x;
    const int cid = blockIdx.x;
    const int j   = cid & (NCHUNK - 1);
    const int bh  = cid >> 6;
    const int b   = bh >> 4;
    const int h   = bh & 15;
    const size_t base = ((size_t)b * LL + (size_t)j * CHUNK) * 1024 + (size_t)h * 64;

    const float* srcs[4] = { k + base, v + base, ig + base, fg + base };
    const int  arr = tid >> 4;
    const int  ch  = tid & 15;
    const bool loader = (tid < 64);
    const float* mySrc = srcs[loader ? arr : 0] + ch * 4;
    const uint32_t mydst0 = (uint32_t)__cvta_generic_to_shared(&stage[0][0][0]) + (arr * 64 + ch * 4) * 4;
    const uint32_t mydst1 = mydst0 + 4 * 64 * 4;

    if (loader) cp16(mydst0, mySrc);
    asm volatile("cp.async.commit_group;\n");

    const int r = tid >> 5;
    const int c = tid & 31;
    float C0[16], C1[16];
#pragma unroll
    for (int i = 0; i < 16; i++) { C0[i] = 0.0f; C1[i] = 0.0f; }
    float nreg = 0.0f, greg = 1.0f;

    for (int t = 0; t < CHUNK; t++) {
        asm volatile("cp.async.wait_group 0;\n" ::: "memory");
        __syncthreads();
        const int cur = t & 1;

        if (t + 1 < CHUNK && loader)
            cp16(cur ? mydst0 : mydst1, mySrc + (size_t)(t + 1) * 1024);
        asm volatile("cp.async.commit_group;\n");

        const float* S   = &stage[cur][0][0];
        const float* ks  = S;
        const float* vs  = S + 64;
        const float* is_ = S + 128;
        const float* fs  = S + 192;

        float v0 = vs[c], v1 = vs[c + 32];

#pragma unroll
        for (int dd = 0; dd < 16; dd += 4) {
            int d = r * 16 + dd;
            float4 f4 = *(const float4*)&fs[d];
            float4 i4 = *(const float4*)&is_[d];
            float4 k4 = *(const float4*)&ks[d];
            float a0 = i4.x * k4.x, a1 = i4.y * k4.y, a2 = i4.z * k4.z, a3 = i4.w * k4.w;
            C0[dd+0] = fmaf(f4.x, C0[dd+0], a0 * v0); C1[dd+0] = fmaf(f4.x, C1[dd+0], a0 * v1);
            C0[dd+1] = fmaf(f4.y, C0[dd+1], a1 * v0); C1[dd+1] = fmaf(f4.y, C1[dd+1], a1 * v1);
            C0[dd+2] = fmaf(f4.z, C0[dd+2], a2 * v0); C1[dd+2] = fmaf(f4.z, C1[dd+2], a2 * v1);
            C0[dd+3] = fmaf(f4.w, C0[dd+3], a3 * v0); C1[dd+3] = fmaf(f4.w, C1[dd+3], a3 * v1);
        }

        if (tid < 64) {
            float ft = fs[tid];
            nreg = fmaf(ft, nreg, is_[tid] * ks[tid]);
            greg *= ft;
        }
        __syncthreads();
    }

    float* dCp = dC + (size_t)cid * 4096;
#pragma unroll
    for (int dd = 0; dd < 16; dd++) {
        dCp[(r * 16 + dd) * 64 + c]      = C0[dd];
        dCp[(r * 16 + dd) * 64 + c + 32] = C1[dd];
    }
    if (tid < 64) {
        dN[(size_t)cid * 64 + tid] = nreg;
        G [(size_t)cid * 64 + tid] = greg;
    }
}

__global__ void __launch_bounds__(128, 1)
chunk_carry(const float* __restrict__ dC, const float* __restrict__ dN,
            const float* __restrict__ G,
            float* __restrict__ Cst, float* __restrict__ Nst)
{
    __shared__ float gs[64], dns[64];
    const int tid = threadIdx.x;
    const int bh  = blockIdx.x;
    const int r = tid >> 5;
    const int c = tid & 31;

    float C0[16], C1[16];
#pragma unroll
    for (int i = 0; i < 16; i++) { C0[i] = 0.0f; C1[i] = 0.0f; }
    float n = 0.0f;

    for (int j = 0; j < NCHUNK; j++) {
        const size_t cid = (size_t)bh * NCHUNK + j;
        float* Cp = Cst + cid * 4096;
        const float* Dp = dC + cid * 4096;

        if (tid < 64) {
            Nst[cid * 64 + tid] = n;
            gs[tid]  = G [cid * 64 + tid];
            dns[tid] = dN[cid * 64 + tid];
        }
#pragma unroll
        for (int dd = 0; dd < 16; dd++) {
            Cp[(r * 16 + dd) * 64 + c]      = C0[dd];
            Cp[(r * 16 + dd) * 64 + c + 32] = C1[dd];
        }
        __syncthreads();
#pragma unroll
        for (int dd = 0; dd < 16; dd++) {
            float gd = gs[r * 16 + dd];
            C0[dd] = fmaf(gd, C0[dd], Dp[(r * 16 + dd) * 64 + c]);
            C1[dd] = fmaf(gd, C1[dd], Dp[(r * 16 + dd) * 64 + c + 32]);
        }
        if (tid < 64) n = fmaf(gs[tid], n, dns[tid]);
        __syncthreads();
    }
}

__global__ void __launch_bounds__(128, 4)
chunk_out(const float* __restrict__ q, const float* __restrict__ k,
          const float* __restrict__ v, const float* __restrict__ ig,
          const float* __restrict__ fg, const float* __restrict__ og,
          const float* __restrict__ xp,
          const float* __restrict__ Cst, const float* __restrict__ Nst,
          __nv_bfloat16* __restrict__ hh, __nv_bfloat16* __restrict__ hl)
{
    __shared__ float stage[2][7][64];
    __shared__ float red[4][64];
    __shared__ float denp[2];

    const int tid = threadIdx.x;
    const int cid = blockIdx.x;
    const int j   = cid & (NCHUNK - 1);
    const int bh  = cid >> 6;
    const int b   = bh >> 4;
    const int h   = bh & 15;
    const size_t base  = ((size_t)b * LL + (size_t)j * CHUNK) * 1024 + (size_t)h * 64;
    const size_t baseg = ((size_t)b * LL + (size_t)j * CHUNK) * 2048 + 1024 + (size_t)h * 64;

    const float* srcs[8] = { q + base, k + base, v + base, ig + base,
                             fg + base, og + base, xp + baseg, q + base };

    const int  arr = tid >> 4;
    const int  ch  = tid & 15;
    const bool loader = (tid < 112);
    const float* mySrc    = srcs[arr] + ch * 4;
    const size_t mystride = (arr == 6) ? 2048 : 1024;
    const uint32_t mydst0 = (uint32_t)__cvta_generic_to_shared(&stage[0][0][0]) + (arr * 64 + ch * 4) * 4;
    const uint32_t mydst1 = mydst0 + 7 * 64 * 4;

    if (loader) cp16(mydst0, mySrc);
    asm volatile("cp.async.commit_group;\n");

    const int r = tid >> 5;
    const int c = tid & 31;

    const float* Cp = Cst + (size_t)cid * 4096;
    float C0[16], C1[16];
#pragma unroll
    for (int dd = 0; dd < 16; dd++) {
        C0[dd] = Cp[(r * 16 + dd) * 64 + c];
        C1[dd] = Cp[(r * 16 + dd) * 64 + c + 32];
    }
    float nreg = (tid < 64) ? Nst[(size_t)cid * 64 + tid] : 0.0f;

    for (int t = 0; t < CHUNK; t++) {
        asm volatile("cp.async.wait_group 0;\n" ::: "memory");
        __syncthreads();
        const int cur = t & 1;

        if (t + 1 < CHUNK && loader)
            cp16(cur ? mydst0 : mydst1, mySrc + (size_t)(t + 1) * mystride);
        asm volatile("cp.async.commit_group;\n");

        const float* S   = &stage[cur][0][0];
        const float* qs  = S;
        const float* ks  = S + 64;
        const float* vs  = S + 128;
        const float* is_ = S + 192;
        const float* fs  = S + 256;
        const float* ogs = S + 320;
        const float* xgs = S + 384;

        float v0 = vs[c], v1 = vs[c + 32];
        float pn0 = 0.0f, pn1 = 0.0f;

#define ROWOP(ff, qq, aa, idx) { float _a = (aa);                              \
        C0[idx] = fmaf((ff), C0[idx], _a * v0); pn0 = fmaf((qq), C0[idx], pn0);\
        C1[idx] = fmaf((ff), C1[idx], _a * v1); pn1 = fmaf((qq), C1[idx], pn1); }

#pragma unroll
        for (int dd = 0; dd < 16; dd += 4) {
            int d = r * 16 + dd;
            float4 f4 = *(const float4*)&fs[d];
            float4 q4 = *(const float4*)&qs[d];
            float4 i4 = *(const float4*)&is_[d];
            float4 k4 = *(const float4*)&ks[d];
            ROWOP(f4.x, q4.x, i4.x * k4.x, dd + 0);
            ROWOP(f4.y, q4.y, i4.y * k4.y, dd + 1);
            ROWOP(f4.z, q4.z, i4.z * k4.z, dd + 2);
            ROWOP(f4.w, q4.w, i4.w * k4.w, dd + 3);
        }
#undef ROWOP

        red[r][c]      = pn0;
        red[r][c + 32] = pn1;

        if (tid < 64) {
            float a = is_[tid] * ks[tid];
            nreg = fmaf(fs[tid], nreg, a);
            float dp = qs[tid] * nreg;
#pragma unroll
            for (int o = 16; o; o >>= 1) dp += __shfl_xor_sync(0xffffffffu, dp, o);
            if ((tid & 31) == 0) denp[tid >> 5] = dp;
        }
        __syncthreads();

        if (tid < 64) {
            float num = red[0][tid] + red[1][tid] + red[2][tid] + red[3][tid];
            float den = fmaxf(denp[0] + denp[1], 1.0f);
            float ov  = (num / den) * ogs[tid] * (1.0f / (1.0f + expf(-xgs[tid])));
            __nv_bfloat16 bh2 = __float2bfloat16_rn(ov);
            __nv_bfloat16 bl2 = __float2bfloat16_rn(ov - __bfloat162float(bh2));
            hh[base + (size_t)t * 1024 + tid] = bh2;
            hl[base + (size_t)t * 1024 + tid] = bl2;
        }
    }
}

// ---------------------------------------------------------------------------
// Launch
// ---------------------------------------------------------------------------
extern "C" void kernel_launch(void* const* d_in, const int* in_sizes, int n_in,
                              void* d_out, int out_size)
{
    const float* x     = (const float*)d_in[0];
    const float* w_in  = (const float*)d_in[1];
    const float* w_q   = (const float*)d_in[2];
    const float* w_k   = (const float*)d_in[3];
    const float* w_v   = (const float*)d_in[4];
    const float* w_i   = (const float*)d_in[5];
    const float* b_i   = (const float*)d_in[6];
    const float* w_f   = (const float*)d_in[7];
    const float* b_f   = (const float*)d_in[8];
    const float* w_o   = (const float*)d_in[9];
    const float* b_o   = (const float*)d_in[10];
    const float* w_qn  = (const float*)d_in[11];
    const float* w_kn  = (const float*)d_in[12];
    const float* w_out = (const float*)d_in[13];
    float* out = (float*)d_out;

    float *xp, *qb, *kb, *vb, *ib, *fb, *ob;
    float *dC, *dN, *G, *Cst, *Nst;
    __nv_bfloat16 *xh, *xl, *xph, *xpl, *hh, *hl, *wih, *wil, *w6h, *w6l, *woh, *wol;
    cudaGetSymbolAddress((void**)&xp, g_xp);
    cudaGetSymbolAddress((void**)&qb, g_q);
    cudaGetSymbolAddress((void**)&kb, g_k);
    cudaGetSymbolAddress((void**)&vb, g_v);
    cudaGetSymbolAddress((void**)&ib, g_i);
    cudaGetSymbolAddress((void**)&fb, g_f);
    cudaGetSymbolAddress((void**)&ob, g_o);
    cudaGetSymbolAddress((void**)&dC, g_dC);
    cudaGetSymbolAddress((void**)&dN, g_dN);
    cudaGetSymbolAddress((void**)&G,  g_G);
    cudaGetSymbolAddress((void**)&Cst, g_Cst);
    cudaGetSymbolAddress((void**)&Nst, g_Nst);
    cudaGetSymbolAddress((void**)&xh,  g_xh);
    cudaGetSymbolAddress((void**)&xl,  g_xl);
    cudaGetSymbolAddress((void**)&xph, g_xph);
    cudaGetSymbolAddress((void**)&xpl, g_xpl);
    cudaGetSymbolAddress((void**)&hh,  g_hh);
    cudaGetSymbolAddress((void**)&hl,  g_hl);
    cudaGetSymbolAddress((void**)&wih, g_wih);
    cudaGetSymbolAddress((void**)&wil, g_wil);
    cudaGetSymbolAddress((void**)&w6h, g_w6h);
    cudaGetSymbolAddress((void**)&w6l, g_w6l);
    cudaGetSymbolAddress((void**)&woh, g_woh);
    cudaGetSymbolAddress((void**)&wol, g_wol);

    cudaFuncSetAttribute(gemm_bf<0,0>, cudaFuncAttributeMaxDynamicSharedMemorySize, GEMM_SMEM);
    cudaFuncSetAttribute(gemm_bf<0,1>, cudaFuncAttributeMaxDynamicSharedMemorySize, GEMM_SMEM);
    cudaFuncSetAttribute(gemm_bf<1,0>, cudaFuncAttributeMaxDynamicSharedMemorySize, GEMM_SMEM);
    cudaFuncSetAttribute(gemm_bf<2,0>, cudaFuncAttributeMaxDynamicSharedMemorySize, GEMM_SMEM);
    cudaFuncSetAttribute(gemm_bf<3,0>, cudaFuncAttributeMaxDynamicSharedMemorySize, GEMM_SMEM);

    // ---- pass 0: operand splits ----
    const int NSQ4 = 1024 * 1024 / 4;   // fp32-quads per 1Mx buffer
    split_k<<<(MROWS * 1024 / 4 + 255) / 256, 256>>>((const float4*)x, (uint2*)xh, (uint2*)xl, MROWS * 1024 / 4);
    split_k<<<(2048 * 1024 / 4 + 255) / 256, 256>>>((const float4*)w_in, (uint2*)wih, (uint2*)wil, 2048 * 1024 / 4);
    const float* w6src[6] = { w_q, w_k, w_v, w_i, w_f, w_o };
    for (int t = 0; t < 6; t++)
        split_k<<<(NSQ4 + 255) / 256, 256>>>((const float4*)w6src[t],
                                             (uint2*)(w6h + (size_t)t * 1024 * 1024),
                                             (uint2*)(w6l + (size_t)t * 1024 * 1024), NSQ4);
    split_k<<<(NSQ4 + 255) / 256, 256>>>((const float4*)w_out, (uint2*)woh, (uint2*)wol, NSQ4);

    dim3 blk(256);
    dim3 gIn(2048 / 128, MROWS / 128);
    dim3 gSq(1024 / 128, MROWS / 128);

    // ---- GEMMs ----
    gemm_bf<0,1><<<gIn, blk, GEMM_SMEM>>>(xh, xl, 1024, wih, wil, nullptr, xp, 2048, xph, xpl);

    const size_t W = (size_t)1024 * 1024;
    gemm_bf<3,0><<<gSq, blk, GEMM_SMEM>>>(xph, xpl, 2048, w6h + 0*W, w6l + 0*W, w_qn, qb, 1024, nullptr, nullptr);
    gemm_bf<3,0><<<gSq, blk, GEMM_SMEM>>>(xph, xpl, 2048, w6h + 1*W, w6l + 1*W, w_kn, kb, 1024, nullptr, nullptr);
    gemm_bf<0,0><<<gSq, blk, GEMM_SMEM>>>(xph, xpl, 2048, w6h + 2*W, w6l + 2*W, nullptr, vb, 1024, nullptr, nullptr);
    gemm_bf<1,0><<<gSq, blk, GEMM_SMEM>>>(xph, xpl, 2048, w6h + 3*W, w6l + 3*W, b_i, ib, 1024, nullptr, nullptr);
    gemm_bf<2,0><<<gSq, blk, GEMM_SMEM>>>(xph, xpl, 2048, w6h + 4*W, w6l + 4*W, b_f, fb, 1024, nullptr, nullptr);
    gemm_bf<2,0><<<gSq, blk, GEMM_SMEM>>>(xph, xpl, 2048, w6h + 5*W, w6l + 5*W, b_o, ob, 1024, nullptr, nullptr);

    // ---- chunk-parallel scan ----
    chunk_fwd  <<<NCID, 128>>>(kb, vb, ib, fb, dC, dN, G);
    chunk_carry<<<BB * NH, 128>>>(dC, dN, G, Cst, Nst);
    chunk_out  <<<NCID, 128>>>(qb, kb, vb, ib, fb, ob, xp, Cst, Nst, hh, hl);

    // ---- output projection ----
    gemm_bf<0,0><<<gSq, blk, GEMM_SMEM>>>(hh, hl, 1024, woh, wol, nullptr, out, 1024, nullptr, nullptr);
}

// round 7
// speedup vs baseline: 3.8747x; 1.1131x over previous
#include <cuda_runtime.h>
#include <cuda_bf16.h>
#include <math.h>
#include <stdint.h>

// Problem constants
#define BB   2
#define LL   4096
#define DIMD 1024
#define NH   16
#define HD   64
#define MROWS (BB * LL)          // 8192
#define KDIM 1024
#define CHUNK  64
#define NCHUNK (LL / CHUNK)      // 64
#define NCID   (BB * NH * NCHUNK) // 2048

// ---------------------------------------------------------------------------
// Scratch
// ---------------------------------------------------------------------------
__device__ float g_xp[(size_t)MROWS * 2048];
__device__ float g_q [(size_t)MROWS * 1024];
__device__ float g_k [(size_t)MROWS * 1024];
__device__ float g_v [(size_t)MROWS * 1024];
__device__ float g_i [(size_t)MROWS * 1024];
__device__ float g_f [(size_t)MROWS * 1024];
__device__ float g_o [(size_t)MROWS * 1024];
// bf16 split operand buffers
__device__ __nv_bfloat16 g_xh [(size_t)MROWS * 1024];
__device__ __nv_bfloat16 g_xl [(size_t)MROWS * 1024];
__device__ __nv_bfloat16 g_xph[(size_t)MROWS * 2048];
__device__ __nv_bfloat16 g_xpl[(size_t)MROWS * 2048];
__device__ __nv_bfloat16 g_hh [(size_t)MROWS * 1024];
__device__ __nv_bfloat16 g_hl [(size_t)MROWS * 1024];
__device__ __nv_bfloat16 g_wih[(size_t)2048 * 1024];
__device__ __nv_bfloat16 g_wil[(size_t)2048 * 1024];
__device__ __nv_bfloat16 g_w6h[(size_t)6 * 1024 * 1024];
__device__ __nv_bfloat16 g_w6l[(size_t)6 * 1024 * 1024];
__device__ __nv_bfloat16 g_woh[(size_t)1024 * 1024];
__device__ __nv_bfloat16 g_wol[(size_t)1024 * 1024];
// chunked-scan scratch
__device__ float g_dC [(size_t)NCID * 4096];
__device__ float g_dN [(size_t)NCID * 64];
__device__ float g_G  [(size_t)NCID * 64];
__device__ float g_Cst[(size_t)NCID * 4096];
__device__ float g_Nst[(size_t)NCID * 64];

// ---------------------------------------------------------------------------
// helpers
// ---------------------------------------------------------------------------
__device__ __forceinline__ uint32_t packbf(float x, float y) {
    __nv_bfloat16 bx = __float2bfloat16_rn(x);
    __nv_bfloat16 by = __float2bfloat16_rn(y);
    return (uint32_t)__bfloat16_as_ushort(bx) | ((uint32_t)__bfloat16_as_ushort(by) << 16);
}
__device__ __forceinline__ uint32_t packlo(float x, float y) {
    __nv_bfloat16 bx = __float2bfloat16_rn(x);
    __nv_bfloat16 by = __float2bfloat16_rn(y);
    return packbf(x - __bfloat162float(bx), y - __bfloat162float(by));
}
__device__ __forceinline__ void cp16(uint32_t s, const void* g)
{
    asm volatile("cp.async.ca.shared.global [%0], [%1], 16;\n" :: "r"(s), "l"(g));
}

#define LDSM_X4(r0, r1, r2, r3, addr) \
    asm volatile("ldmatrix.sync.aligned.m8n8.x4.shared.b16 {%0,%1,%2,%3}, [%4];" \
                 : "=r"(r0), "=r"(r1), "=r"(r2), "=r"(r3) : "r"(addr))

#define MMA_BF16(d, a, b0, b1) \
    asm volatile("mma.sync.aligned.m16n8k16.row.col.f32.bf16.bf16.f32 " \
                 "{%0,%1,%2,%3}, {%4,%5,%6,%7}, {%8,%9}, {%0,%1,%2,%3};" \
                 : "+f"((d)[0]), "+f"((d)[1]), "+f"((d)[2]), "+f"((d)[3]) \
                 : "r"((a)[0]), "r"((a)[1]), "r"((a)[2]), "r"((a)[3]), \
                   "r"(b0), "r"(b1))

// ---------------------------------------------------------------------------
// Pass 0: fp32 -> (hi, lo) bf16 split, vectorized
// ---------------------------------------------------------------------------
__global__ void split_k(const float4* __restrict__ s, uint2* __restrict__ hi,
                        uint2* __restrict__ lo, int n4)
{
    int i = blockIdx.x * 256 + threadIdx.x;
    if (i >= n4) return;
    float4 v = s[i];
    uint2 h, l;
    h.x = packbf(v.x, v.y); h.y = packbf(v.z, v.w);
    l.x = packlo(v.x, v.y); l.y = packlo(v.z, v.w);
    hi[i] = h; lo[i] = l;
}

// ---------------------------------------------------------------------------
// cp.async pipelined split-bf16 GEMM.  (R7: warp tile 64x64, 4 warps, 3 stages)
// C[M,N] = (Ah+Al)[M,K] @ (Bh+Bl)[N,K]^T (3-term), K=1024, CTA 128x128, BK=32.
// smem/stage: Ah|Al|Bh|Bl, each 128 rows x 64B (SW64 swizzled) = 32KB; 3 stages
// -> 96KB smem, 2 CTAs/SM.
// ACT: 0 none, 1 exp(+bias), 2 sigmoid(+bias), 3 rmsnorm(head=64, w=bias)
// SPLIT: also emit bf16 hi/lo of output.
// ---------------------------------------------------------------------------
#define STAGES 3
#define SECB   8192
#define STAGEB 32768
#define GEMM_SMEM (STAGES * STAGEB)   // 98304

template <int ACT, int SPLIT>
__global__ void __launch_bounds__(128, 2)
gemm_bf(const __nv_bfloat16* __restrict__ Ah, const __nv_bfloat16* __restrict__ Al, int lda,
        const __nv_bfloat16* __restrict__ Bh, const __nv_bfloat16* __restrict__ Bl,
        const float* __restrict__ bias,
        float* __restrict__ C, int ldc,
        __nv_bfloat16* __restrict__ Chh, __nv_bfloat16* __restrict__ Cll)
{
    extern __shared__ __align__(128) char smem[];
    const uint32_t sbase = (uint32_t)__cvta_generic_to_shared(smem);

    const int tid  = threadIdx.x;
    const int w    = tid >> 5;
    const int lane = tid & 31;
    const int wm   = w & 1;          // M half (64 rows)
    const int wn   = w >> 1;         // N half (64 cols)

    const int m0 = blockIdx.y * 128;
    const int n0 = blockIdx.x * 128;

    const __nv_bfloat16* Ahp = Ah + (size_t)m0 * lda;
    const __nv_bfloat16* Alp = Al + (size_t)m0 * lda;
    const __nv_bfloat16* Bhp = Bh + (size_t)n0 * KDIM;
    const __nv_bfloat16* Blp = Bl + (size_t)n0 * KDIM;

    // loader: 2048 16B chunks / stage, 16 per thread
    auto load_stage = [&](int buf, int k0) {
        const uint32_t db = sbase + (uint32_t)(buf * STAGEB);
#pragma unroll
        for (int i = 0; i < 16; i++) {
            const int ci  = tid + i * 128;
            const int sec = ci >> 9;
            const int r   = (ci >> 2) & 127;
            const int kq  = ci & 3;
            const __nv_bfloat16* gp;
            if      (sec == 0) gp = Ahp + (size_t)r * lda;
            else if (sec == 1) gp = Alp + (size_t)r * lda;
            else if (sec == 2) gp = Bhp + (size_t)r * KDIM;
            else               gp = Blp + (size_t)r * KDIM;
            gp += k0 + kq * 8;
            const uint32_t d = db + (uint32_t)(sec * SECB + r * 64 + ((kq * 16) ^ ((r * 8) & 0x30)));
            cp16(d, gp);
        }
    };

    // ldmatrix per-lane addressing (SW64 rows: 64B, XOR bits[5:4] with row bits[2:1])
    const int a_r  = (lane & 7) + ((lane >> 3) & 1) * 8;
    const int ak2  = ((lane >> 4) & 1) * 16;
    const uint32_t axr = (uint32_t)((a_r << 3) & 0x30);
    const int g    = lane >> 3;
    const int b_r  = ((g >> 1) * 8) + (lane & 7);
    const int bk2  = (g & 1) * 16;
    const uint32_t bxr = (uint32_t)((b_r << 3) & 0x30);

    uint32_t aoff[4], boff[4];
#pragma unroll
    for (int mi = 0; mi < 4; mi++) aoff[mi] = (uint32_t)((wm * 64 + mi * 16 + a_r) * 64);
#pragma unroll
    for (int gi = 0; gi < 4; gi++) boff[gi] = (uint32_t)(2 * SECB + (wn * 64 + gi * 16 + b_r) * 64);

    float acc[4][8][4] = {};

    load_stage(0, 0);
    asm volatile("cp.async.commit_group;\n");
    load_stage(1, 32);
    asm volatile("cp.async.commit_group;\n");

    const int S = KDIM / 32;   // 32
    for (int s = 0; s < S; s++) {
        asm volatile("cp.async.wait_group 1;\n" ::: "memory");
        __syncthreads();
        // buffer (s+2)%3 was consumed in iteration s-1 -> safe to overwrite
        if (s + 2 < S) load_stage((s + 2) % STAGES, (s + 2) * 32);
        asm volatile("cp.async.commit_group;\n");

        const uint32_t bb = sbase + (uint32_t)((s % STAGES) * STAGEB);
#pragma unroll
        for (int kb = 0; kb < 2; kb++) {
            uint32_t Ahf[4][4], Alf[4][4];
#pragma unroll
            for (int mi = 0; mi < 4; mi++) {
                const uint32_t aa = bb + aoff[mi] + (uint32_t)((kb * 32 + ak2) ^ axr);
                LDSM_X4(Ahf[mi][0], Ahf[mi][1], Ahf[mi][2], Ahf[mi][3], aa);
                LDSM_X4(Alf[mi][0], Alf[mi][1], Alf[mi][2], Alf[mi][3], aa + SECB);
            }
#pragma unroll
            for (int gi = 0; gi < 4; gi++) {
                uint32_t Bhf[4], Blf[4];
                const uint32_t ba = bb + boff[gi] + (uint32_t)((kb * 32 + bk2) ^ bxr);
                LDSM_X4(Bhf[0], Bhf[1], Bhf[2], Bhf[3], ba);
                LDSM_X4(Blf[0], Blf[1], Blf[2], Blf[3], ba + SECB);
#pragma unroll
                for (int mi = 0; mi < 4; mi++)
#pragma unroll
                    for (int hf = 0; hf < 2; hf++) {
                        float* d = acc[mi][gi * 2 + hf];
                        MMA_BF16(d, Ahf[mi], Bhf[2 * hf], Bhf[2 * hf + 1]);
                        MMA_BF16(d, Ahf[mi], Blf[2 * hf], Blf[2 * hf + 1]);
                        MMA_BF16(d, Alf[mi], Bhf[2 * hf], Bhf[2 * hf + 1]);
                    }
            }
        }
    }

    const int qr = lane >> 2;
    const int qc = (lane & 3) * 2;

    // fused per-head RMSNorm: warp column range = exactly one 64-dim head
    if (ACT == 3) {
#pragma unroll
        for (int mi = 0; mi < 4; mi++)
#pragma unroll
            for (int rh = 0; rh < 2; rh++) {
                float ss = 0.0f;
#pragma unroll
                for (int ti = 0; ti < 8; ti++) {
                    float a = acc[mi][ti][2 * rh], b2 = acc[mi][ti][2 * rh + 1];
                    ss += a * a + b2 * b2;
                }
                ss += __shfl_xor_sync(0xffffffffu, ss, 1);
                ss += __shfl_xor_sync(0xffffffffu, ss, 2);
                const float sc = rsqrtf(ss * (1.0f / 64.0f) + 1e-6f);
#pragma unroll
                for (int ti = 0; ti < 8; ti++) {
                    acc[mi][ti][2 * rh]     *= sc * bias[ti * 8 + qc];
                    acc[mi][ti][2 * rh + 1] *= sc * bias[ti * 8 + qc + 1];
                }
            }
    }

#pragma unroll
    for (int mi = 0; mi < 4; mi++) {
#pragma unroll
        for (int ti = 0; ti < 8; ti++) {
            const int col = n0 + wn * 64 + ti * 8 + qc;
            float bcol0 = 0.f, bcol1 = 0.f;
            if (ACT == 1 || ACT == 2) { bcol0 = bias[col]; bcol1 = bias[col + 1]; }
#pragma unroll
            for (int rh = 0; rh < 2; rh++) {
                const int row = m0 + wm * 64 + mi * 16 + rh * 8 + qr;
                float x0 = acc[mi][ti][2 * rh + 0];
                float x1 = acc[mi][ti][2 * rh + 1];
                if (ACT == 1)      { x0 = expf(x0 + bcol0); x1 = expf(x1 + bcol1); }
                else if (ACT == 2) { x0 = 1.0f / (1.0f + expf(-(x0 + bcol0)));
                                     x1 = 1.0f / (1.0f + expf(-(x1 + bcol1))); }
                *(float2*)&C[(size_t)row * ldc + col] = make_float2(x0, x1);
                if (SPLIT) {
                    *(uint32_t*)&Chh[(size_t)row * ldc + col] = packbf(x0, x1);
                    *(uint32_t*)&Cll[(size_t)row * ldc + col] = packlo(x0, x1);
                }
            }
        }
    }
}

// ---------------------------------------------------------------------------
// Chunk-parallel mLSTM scan (unchanged from R6)
// ---------------------------------------------------------------------------
__global__ void __launch_bounds__(128, 4)
chunk_fwd(const float* __restrict__ k, const float* __restrict__ v,
          const float* __restrict__ ig, const float* __restrict__ fg,
          float* __restrict__ dC, float* __restrict__ dN, float* __restrict__ G)
{
    __shared__ float stage[2][4][64];

    const int tid = threadIdx.x;
    const int cid = blockIdx.x;
    const int j   = cid & (NCHUNK - 1);
    const int bh  = cid >> 6;
    const int b   = bh >> 4;
    const int h   = bh & 15;
    const size_t base = ((size_t)b * LL + (size_t)j * CHUNK) * 1024 + (size_t)h * 64;

    const float* srcs[4] = { k + base, v + base, ig + base, fg + base };
    const int  arr = tid >> 4;
    const int  ch  = tid & 15;
    const bool loader = (tid < 64);
    const float* mySrc = srcs[loader ? arr : 0] + ch * 4;
    const uint32_t mydst0 = (uint32_t)__cvta_generic_to_shared(&stage[0][0][0]) + (arr * 64 + ch * 4) * 4;
    const uint32_t mydst1 = mydst0 + 4 * 64 * 4;

    if (loader) cp16(mydst0, mySrc);
    asm volatile("cp.async.commit_group;\n");

    const int r = tid >> 5;
    const int c = tid & 31;
    float C0[16], C1[16];
#pragma unroll
    for (int i = 0; i < 16; i++) { C0[i] = 0.0f; C1[i] = 0.0f; }
    float nreg = 0.0f, greg = 1.0f;

    for (int t = 0; t < CHUNK; t++) {
        asm volatile("cp.async.wait_group 0;\n" ::: "memory");
        __syncthreads();
        const int cur = t & 1;

        if (t + 1 < CHUNK && loader)
            cp16(cur ? mydst0 : mydst1, mySrc + (size_t)(t + 1) * 1024);
        asm volatile("cp.async.commit_group;\n");

        const float* S   = &stage[cur][0][0];
        const float* ks  = S;
        const float* vs  = S + 64;
        const float* is_ = S + 128;
        const float* fs  = S + 192;

        float v0 = vs[c], v1 = vs[c + 32];

#pragma unroll
        for (int dd = 0; dd < 16; dd += 4) {
            int d = r * 16 + dd;
            float4 f4 = *(const float4*)&fs[d];
            float4 i4 = *(const float4*)&is_[d];
            float4 k4 = *(const float4*)&ks[d];
            float a0 = i4.x * k4.x, a1 = i4.y * k4.y, a2 = i4.z * k4.z, a3 = i4.w * k4.w;
            C0[dd+0] = fmaf(f4.x, C0[dd+0], a0 * v0); C1[dd+0] = fmaf(f4.x, C1[dd+0], a0 * v1);
            C0[dd+1] = fmaf(f4.y, C0[dd+1], a1 * v0); C1[dd+1] = fmaf(f4.y, C1[dd+1], a1 * v1);
            C0[dd+2] = fmaf(f4.z, C0[dd+2], a2 * v0); C1[dd+2] = fmaf(f4.z, C1[dd+2], a2 * v1);
            C0[dd+3] = fmaf(f4.w, C0[dd+3], a3 * v0); C1[dd+3] = fmaf(f4.w, C1[dd+3], a3 * v1);
        }

        if (tid < 64) {
            float ft = fs[tid];
            nreg = fmaf(ft, nreg, is_[tid] * ks[tid]);
            greg *= ft;
        }
        __syncthreads();
    }

    float* dCp = dC + (size_t)cid * 4096;
#pragma unroll
    for (int dd = 0; dd < 16; dd++) {
        dCp[(r * 16 + dd) * 64 + c]      = C0[dd];
        dCp[(r * 16 + dd) * 64 + c + 32] = C1[dd];
    }
    if (tid < 64) {
        dN[(size_t)cid * 64 + tid] = nreg;
        G [(size_t)cid * 64 + tid] = greg;
    }
}

__global__ void __launch_bounds__(128, 1)
chunk_carry(const float* __restrict__ dC, const float* __restrict__ dN,
            const float* __restrict__ G,
            float* __restrict__ Cst, float* __restrict__ Nst)
{
    __shared__ float gs[64], dns[64];
    const int tid = threadIdx.x;
    const int bh  = blockIdx.x;
    const int r = tid >> 5;
    const int c = tid & 31;

    float C0[16], C1[16];
#pragma unroll
    for (int i = 0; i < 16; i++) { C0[i] = 0.0f; C1[i] = 0.0f; }
    float n = 0.0f;

    for (int j = 0; j < NCHUNK; j++) {
        const size_t cid = (size_t)bh * NCHUNK + j;
        float* Cp = Cst + cid * 4096;
        const float* Dp = dC + cid * 4096;

        if (tid < 64) {
            Nst[cid * 64 + tid] = n;
            gs[tid]  = G [cid * 64 + tid];
            dns[tid] = dN[cid * 64 + tid];
        }
#pragma unroll
        for (int dd = 0; dd < 16; dd++) {
            Cp[(r * 16 + dd) * 64 + c]      = C0[dd];
            Cp[(r * 16 + dd) * 64 + c + 32] = C1[dd];
        }
        __syncthreads();
#pragma unroll
        for (int dd = 0; dd < 16; dd++) {
            float gd = gs[r * 16 + dd];
            C0[dd] = fmaf(gd, C0[dd], Dp[(r * 16 + dd) * 64 + c]);
            C1[dd] = fmaf(gd, C1[dd], Dp[(r * 16 + dd) * 64 + c + 32]);
        }
        if (tid < 64) n = fmaf(gs[tid], n, dns[tid]);
        __syncthreads();
    }
}

__global__ void __launch_bounds__(128, 4)
chunk_out(const float* __restrict__ q, const float* __restrict__ k,
          const float* __restrict__ v, const float* __restrict__ ig,
          const float* __restrict__ fg, const float* __restrict__ og,
          const float* __restrict__ xp,
          const float* __restrict__ Cst, const float* __restrict__ Nst,
          __nv_bfloat16* __restrict__ hh, __nv_bfloat16* __restrict__ hl)
{
    __shared__ float stage[2][7][64];
    __shared__ float red[4][64];
    __shared__ float denp[2];

    const int tid = threadIdx.x;
    const int cid = blockIdx.x;
    const int j   = cid & (NCHUNK - 1);
    const int bh  = cid >> 6;
    const int b   = bh >> 4;
    const int h   = bh & 15;
    const size_t base  = ((size_t)b * LL + (size_t)j * CHUNK) * 1024 + (size_t)h * 64;
    const size_t baseg = ((size_t)b * LL + (size_t)j * CHUNK) * 2048 + 1024 + (size_t)h * 64;

    const float* srcs[8] = { q + base, k + base, v + base, ig + base,
                             fg + base, og + base, xp + baseg, q + base };

    const int  arr = tid >> 4;
    const int  ch  = tid & 15;
    const bool loader = (tid < 112);
    const float* mySrc    = srcs[arr] + ch * 4;
    const size_t mystride = (arr == 6) ? 2048 : 1024;
    const uint32_t mydst0 = (uint32_t)__cvta_generic_to_shared(&stage[0][0][0]) + (arr * 64 + ch * 4) * 4;
    const uint32_t mydst1 = mydst0 + 7 * 64 * 4;

    if (loader) cp16(mydst0, mySrc);
    asm volatile("cp.async.commit_group;\n");

    const int r = tid >> 5;
    const int c = tid & 31;

    const float* Cp = Cst + (size_t)cid * 4096;
    float C0[16], C1[16];
#pragma unroll
    for (int dd = 0; dd < 16; dd++) {
        C0[dd] = Cp[(r * 16 + dd) * 64 + c];
        C1[dd] = Cp[(r * 16 + dd) * 64 + c + 32];
    }
    float nreg = (tid < 64) ? Nst[(size_t)cid * 64 + tid] : 0.0f;

    for (int t = 0; t < CHUNK; t++) {
        asm volatile("cp.async.wait_group 0;\n" ::: "memory");
        __syncthreads();
        const int cur = t & 1;

        if (t + 1 < CHUNK && loader)
            cp16(cur ? mydst0 : mydst1, mySrc + (size_t)(t + 1) * mystride);
        asm volatile("cp.async.commit_group;\n");

        const float* S   = &stage[cur][0][0];
        const float* qs  = S;
        const float* ks  = S + 64;
        const float* vs  = S + 128;
        const float* is_ = S + 192;
        const float* fs  = S + 256;
        const float* ogs = S + 320;
        const float* xgs = S + 384;

        float v0 = vs[c], v1 = vs[c + 32];
        float pn0 = 0.0f, pn1 = 0.0f;

#define ROWOP(ff, qq, aa, idx) { float _a = (aa);                              \
        C0[idx] = fmaf((ff), C0[idx], _a * v0); pn0 = fmaf((qq), C0[idx], pn0);\
        C1[idx] = fmaf((ff), C1[idx], _a * v1); pn1 = fmaf((qq), C1[idx], pn1); }

#pragma unroll
        for (int dd = 0; dd < 16; dd += 4) {
            int d = r * 16 + dd;
            float4 f4 = *(const float4*)&fs[d];
            float4 q4 = *(const float4*)&qs[d];
            float4 i4 = *(const float4*)&is_[d];
            float4 k4 = *(const float4*)&ks[d];
            ROWOP(f4.x, q4.x, i4.x * k4.x, dd + 0);
            ROWOP(f4.y, q4.y, i4.y * k4.y, dd + 1);
            ROWOP(f4.z, q4.z, i4.z * k4.z, dd + 2);
            ROWOP(f4.w, q4.w, i4.w * k4.w, dd + 3);
        }
#undef ROWOP

        red[r][c]      = pn0;
        red[r][c + 32] = pn1;

        if (tid < 64) {
            float a = is_[tid] * ks[tid];
            nreg = fmaf(fs[tid], nreg, a);
            float dp = qs[tid] * nreg;
#pragma unroll
            for (int o = 16; o; o >>= 1) dp += __shfl_xor_sync(0xffffffffu, dp, o);
            if ((tid & 31) == 0) denp[tid >> 5] = dp;
        }
        __syncthreads();

        if (tid < 64) {
            float num = red[0][tid] + red[1][tid] + red[2][tid] + red[3][tid];
            float den = fmaxf(denp[0] + denp[1], 1.0f);
            float ov  = (num / den) * ogs[tid] * (1.0f / (1.0f + expf(-xgs[tid])));
            __nv_bfloat16 bh2 = __float2bfloat16_rn(ov);
            __nv_bfloat16 bl2 = __float2bfloat16_rn(ov - __bfloat162float(bh2));
            hh[base + (size_t)t * 1024 + tid] = bh2;
            hl[base + (size_t)t * 1024 + tid] = bl2;
        }
    }
}

// ---------------------------------------------------------------------------
// Launch
// ---------------------------------------------------------------------------
extern "C" void kernel_launch(void* const* d_in, const int* in_sizes, int n_in,
                              void* d_out, int out_size)
{
    const float* x     = (const float*)d_in[0];
    const float* w_in  = (const float*)d_in[1];
    const float* w_q   = (const float*)d_in[2];
    const float* w_k   = (const float*)d_in[3];
    const float* w_v   = (const float*)d_in[4];
    const float* w_i   = (const float*)d_in[5];
    const float* b_i   = (const float*)d_in[6];
    const float* w_f   = (const float*)d_in[7];
    const float* b_f   = (const float*)d_in[8];
    const float* w_o   = (const float*)d_in[9];
    const float* b_o   = (const float*)d_in[10];
    const float* w_qn  = (const float*)d_in[11];
    const float* w_kn  = (const float*)d_in[12];
    const float* w_out = (const float*)d_in[13];
    float* out = (float*)d_out;

    float *xp, *qb, *kb, *vb, *ib, *fb, *ob;
    float *dC, *dN, *G, *Cst, *Nst;
    __nv_bfloat16 *xh, *xl, *xph, *xpl, *hh, *hl, *wih, *wil, *w6h, *w6l, *woh, *wol;
    cudaGetSymbolAddress((void**)&xp, g_xp);
    cudaGetSymbolAddress((void**)&qb, g_q);
    cudaGetSymbolAddress((void**)&kb, g_k);
    cudaGetSymbolAddress((void**)&vb, g_v);
    cudaGetSymbolAddress((void**)&ib, g_i);
    cudaGetSymbolAddress((void**)&fb, g_f);
    cudaGetSymbolAddress((void**)&ob, g_o);
    cudaGetSymbolAddress((void**)&dC, g_dC);
    cudaGetSymbolAddress((void**)&dN, g_dN);
    cudaGetSymbolAddress((void**)&G,  g_G);
    cudaGetSymbolAddress((void**)&Cst, g_Cst);
    cudaGetSymbolAddress((void**)&Nst, g_Nst);
    cudaGetSymbolAddress((void**)&xh,  g_xh);
    cudaGetSymbolAddress((void**)&xl,  g_xl);
    cudaGetSymbolAddress((void**)&xph, g_xph);
    cudaGetSymbolAddress((void**)&xpl, g_xpl);
    cudaGetSymbolAddress((void**)&hh,  g_hh);
    cudaGetSymbolAddress((void**)&hl,  g_hl);
    cudaGetSymbolAddress((void**)&wih, g_wih);
    cudaGetSymbolAddress((void**)&wil, g_wil);
    cudaGetSymbolAddress((void**)&w6h, g_w6h);
    cudaGetSymbolAddress((void**)&w6l, g_w6l);
    cudaGetSymbolAddress((void**)&woh, g_woh);
    cudaGetSymbolAddress((void**)&wol, g_wol);

    cudaFuncSetAttribute(gemm_bf<0,0>, cudaFuncAttributeMaxDynamicSharedMemorySize, GEMM_SMEM);
    cudaFuncSetAttribute(gemm_bf<0,1>, cudaFuncAttributeMaxDynamicSharedMemorySize, GEMM_SMEM);
    cudaFuncSetAttribute(gemm_bf<1,0>, cudaFuncAttributeMaxDynamicSharedMemorySize, GEMM_SMEM);
    cudaFuncSetAttribute(gemm_bf<2,0>, cudaFuncAttributeMaxDynamicSharedMemorySize, GEMM_SMEM);
    cudaFuncSetAttribute(gemm_bf<3,0>, cudaFuncAttributeMaxDynamicSharedMemorySize, GEMM_SMEM);

    // ---- pass 0: operand splits ----
    const int NSQ4 = 1024 * 1024 / 4;
    split_k<<<(MROWS * 1024 / 4 + 255) / 256, 256>>>((const float4*)x, (uint2*)xh, (uint2*)xl, MROWS * 1024 / 4);
    split_k<<<(2048 * 1024 / 4 + 255) / 256, 256>>>((const float4*)w_in, (uint2*)wih, (uint2*)wil, 2048 * 1024 / 4);
    const float* w6src[6] = { w_q, w_k, w_v, w_i, w_f, w_o };
    for (int t = 0; t < 6; t++)
        split_k<<<(NSQ4 + 255) / 256, 256>>>((const float4*)w6src[t],
                                             (uint2*)(w6h + (size_t)t * 1024 * 1024),
                                             (uint2*)(w6l + (size_t)t * 1024 * 1024), NSQ4);
    split_k<<<(NSQ4 + 255) / 256, 256>>>((const float4*)w_out, (uint2*)woh, (uint2*)wol, NSQ4);

    dim3 blk(128);
    dim3 gIn(2048 / 128, MROWS / 128);
    dim3 gSq(1024 / 128, MROWS / 128);

    // ---- GEMMs ----
    gemm_bf<0,1><<<gIn, blk, GEMM_SMEM>>>(xh, xl, 1024, wih, wil, nullptr, xp, 2048, xph, xpl);

    const size_t W = (size_t)1024 * 1024;
    gemm_bf<3,0><<<gSq, blk, GEMM_SMEM>>>(xph, xpl, 2048, w6h + 0*W, w6l + 0*W, w_qn, qb, 1024, nullptr, nullptr);
    gemm_bf<3,0><<<gSq, blk, GEMM_SMEM>>>(xph, xpl, 2048, w6h + 1*W, w6l + 1*W, w_kn, kb, 1024, nullptr, nullptr);
    gemm_bf<0,0><<<gSq, blk, GEMM_SMEM>>>(xph, xpl, 2048, w6h + 2*W, w6l + 2*W, nullptr, vb, 1024, nullptr, nullptr);
    gemm_bf<1,0><<<gSq, blk, GEMM_SMEM>>>(xph, xpl, 2048, w6h + 3*W, w6l + 3*W, b_i, ib, 1024, nullptr, nullptr);
    gemm_bf<2,0><<<gSq, blk, GEMM_SMEM>>>(xph, xpl, 2048, w6h + 4*W, w6l + 4*W, b_f, fb, 1024, nullptr, nullptr);
    gemm_bf<2,0><<<gSq, blk, GEMM_SMEM>>>(xph, xpl, 2048, w6h + 5*W, w6l + 5*W, b_o, ob, 1024, nullptr, nullptr);

    // ---- chunk-parallel scan ----
    chunk_fwd  <<<NCID, 128>>>(kb, vb, ib, fb, dC, dN, G);
    chunk_carry<<<BB * NH, 128>>>(dC, dN, G, Cst, Nst);
    chunk_out  <<<NCID, 128>>>(qb, kb, vb, ib, fb, ob, xp, Cst, Nst, hh, hl);

    // ---- output projection ----
    gemm_bf<0,0><<<gSq, blk, GEMM_SMEM>>>(hh, hl, 1024, woh, wol, nullptr, out, 1024, nullptr, nullptr);
}

// round 8
// speedup vs baseline: 5.0385x; 1.3004x over previous
#include <cuda_runtime.h>
#include <cuda_fp16.h>
#include <math.h>
#include <stdint.h>

// Problem constants
#define BB   2
#define LL   4096
#define DIMD 1024
#define NH   16
#define HD   64
#define MROWS (BB * LL)          // 8192
#define KDIM 1024
#define CHUNK  64
#define NCHUNK (LL / CHUNK)      // 64
#define NCID   (BB * NH * NCHUNK) // 2048
#define NPJ  6144                // fused projection width

// ---------------------------------------------------------------------------
// Scratch
// ---------------------------------------------------------------------------
__device__ float g_xp[(size_t)MROWS * 2048];
__device__ float g_pj[(size_t)MROWS * NPJ];   // q|k|v|i|f|o fused, ld=6144
// fp16 split operand buffers
__device__ __half g_xh [(size_t)MROWS * 1024];
__device__ __half g_xl [(size_t)MROWS * 1024];
__device__ __half g_xph[(size_t)MROWS * 2048];
__device__ __half g_xpl[(size_t)MROWS * 2048];
__device__ __half g_hh [(size_t)MROWS * 1024];
__device__ __half g_hl [(size_t)MROWS * 1024];
__device__ __half g_wif[(size_t)2048 * 1024];
__device__ __half g_w6f[(size_t)6 * 1024 * 1024];
__device__ __half g_wof[(size_t)1024 * 1024];
// chunked-scan scratch
__device__ float g_dC [(size_t)NCID * 4096];
__device__ float g_dN [(size_t)NCID * 64];
__device__ float g_G  [(size_t)NCID * 64];
__device__ float g_Cst[(size_t)NCID * 4096];
__device__ float g_Nst[(size_t)NCID * 64];

// ---------------------------------------------------------------------------
// helpers
// ---------------------------------------------------------------------------
__device__ __forceinline__ uint32_t packh(float x, float y) {
    __half hx = __float2half_rn(x);
    __half hy = __float2half_rn(y);
    return (uint32_t)__half_as_ushort(hx) | ((uint32_t)__half_as_ushort(hy) << 16);
}
__device__ __forceinline__ uint32_t packhl(float x, float y) {
    __half hx = __float2half_rn(x);
    __half hy = __float2half_rn(y);
    return packh(x - __half2float(hx), y - __half2float(hy));
}
__device__ __forceinline__ void cp16(uint32_t s, const void* g)
{
    asm volatile("cp.async.ca.shared.global [%0], [%1], 16;\n" :: "r"(s), "l"(g));
}

#define LDSM_X4(r0, r1, r2, r3, addr) \
    asm volatile("ldmatrix.sync.aligned.m8n8.x4.shared.b16 {%0,%1,%2,%3}, [%4];" \
                 : "=r"(r0), "=r"(r1), "=r"(r2), "=r"(r3) : "r"(addr))

#define MMA_F16(d, a, b0, b1) \
    asm volatile("mma.sync.aligned.m16n8k16.row.col.f32.f16.f16.f32 " \
                 "{%0,%1,%2,%3}, {%4,%5,%6,%7}, {%8,%9}, {%0,%1,%2,%3};" \
                 : "+f"((d)[0]), "+f"((d)[1]), "+f"((d)[2]), "+f"((d)[3]) \
                 : "r"((a)[0]), "r"((a)[1]), "r"((a)[2]), "r"((a)[3]), \
                   "r"(b0), "r"(b1))

// ---------------------------------------------------------------------------
// Pass 0a: fp32 -> (hi, lo) fp16 split (for x)
// ---------------------------------------------------------------------------
__global__ void split_h(const float4* __restrict__ s, uint2* __restrict__ hi,
                        uint2* __restrict__ lo, int n4)
{
    int i = blockIdx.x * 256 + threadIdx.x;
    if (i >= n4) return;
    float4 v = s[i];
    uint2 h, l;
    h.x = packh(v.x, v.y);  h.y = packh(v.z, v.w);
    l.x = packhl(v.x, v.y); l.y = packhl(v.z, v.w);
    hi[i] = h; lo[i] = l;
}

// Pass 0b: fp32 -> fp16 (weights, single term)
__global__ void cvt_h(const float4* __restrict__ s, uint2* __restrict__ d, int n4)
{
    int i = blockIdx.x * 256 + threadIdx.x;
    if (i >= n4) return;
    float4 v = s[i];
    uint2 o;
    o.x = packh(v.x, v.y); o.y = packh(v.z, v.w);
    d[i] = o;
}

// ---------------------------------------------------------------------------
// cp.async pipelined fp16 2-MMA GEMM.
// C[M,N] = (Ah+Al)[M,K] @ B[N,K]^T, K=1024, CTA 128x128, warp 64x64, BK=32.
// smem/stage: Ah|Al|B, each 128 rows x 64B (SW64) = 24KB; 4 stages = 96KB,
// 2 CTAs/SM.
// MODE 0: in_proj  -> fp32 C (ldc) + fp16 hi/lo split outputs
// MODE 1: fused projections, N=6144: per-1024-col-segment epilogue:
//         seg0/1 rmsnorm(q0/q1), seg2 none, seg3 exp+q2, seg4 sigm+q3, seg5 sigm+q4
// MODE 2: plain fp32 C
// ---------------------------------------------------------------------------
#define STAGES 4
#define SECB   8192
#define STAGEB (3 * SECB)             // 24576
#define GEMM_SMEM (STAGES * STAGEB)   // 98304

template <int MODE>
__global__ void __launch_bounds__(128, 2)
gemm_f16(const __half* __restrict__ Ah, const __half* __restrict__ Al, int lda,
         const __half* __restrict__ B,
         const float* __restrict__ q0, const float* __restrict__ q1,
         const float* __restrict__ q2, const float* __restrict__ q3,
         const float* __restrict__ q4,
         float* __restrict__ C, int ldc,
         __half* __restrict__ Chh, __half* __restrict__ Cll)
{
    extern __shared__ __align__(128) char smem[];
    const uint32_t sbase = (uint32_t)__cvta_generic_to_shared(smem);

    const int tid  = threadIdx.x;
    const int w    = tid >> 5;
    const int lane = tid & 31;
    const int wm   = w & 1;          // M half (64 rows)
    const int wn   = w >> 1;         // N half (64 cols)

    const int m0 = blockIdx.y * 128;
    const int n0 = blockIdx.x * 128;

    const __half* Ahp = Ah + (size_t)m0 * lda;
    const __half* Alp = Al + (size_t)m0 * lda;
    const __half* Bp  = B  + (size_t)n0 * KDIM;

    // loader: 1536 16B chunks / stage, 12 per thread
    auto load_stage = [&](int buf, int k0) {
        const uint32_t db = sbase + (uint32_t)(buf * STAGEB);
#pragma unroll
        for (int i = 0; i < 12; i++) {
            const int ci  = tid + i * 128;
            const int sec = ci >> 9;          // 0=Ah 1=Al 2=B
            const int r   = (ci >> 2) & 127;
            const int kq  = ci & 3;
            const __half* gp;
            if      (sec == 0) gp = Ahp + (size_t)r * lda;
            else if (sec == 1) gp = Alp + (size_t)r * lda;
            else               gp = Bp  + (size_t)r * KDIM;
            gp += k0 + kq * 8;
            const uint32_t d = db + (uint32_t)(sec * SECB + r * 64 + ((kq * 16) ^ ((r * 8) & 0x30)));
            cp16(d, gp);
        }
    };

    // ldmatrix per-lane addressing (SW64)
    const int a_r  = (lane & 7) + ((lane >> 3) & 1) * 8;
    const int ak2  = ((lane >> 4) & 1) * 16;
    const uint32_t axr = (uint32_t)((a_r << 3) & 0x30);
    const int g    = lane >> 3;
    const int b_r  = ((g >> 1) * 8) + (lane & 7);
    const int bk2  = (g & 1) * 16;
    const uint32_t bxr = (uint32_t)((b_r << 3) & 0x30);

    uint32_t aoff[4], boff[4];
#pragma unroll
    for (int mi = 0; mi < 4; mi++) aoff[mi] = (uint32_t)((wm * 64 + mi * 16 + a_r) * 64);
#pragma unroll
    for (int gi = 0; gi < 4; gi++) boff[gi] = (uint32_t)(2 * SECB + (wn * 64 + gi * 16 + b_r) * 64);

    float acc[4][8][4] = {};

    load_stage(0, 0);
    asm volatile("cp.async.commit_group;\n");
    load_stage(1, 32);
    asm volatile("cp.async.commit_group;\n");
    load_stage(2, 64);
    asm volatile("cp.async.commit_group;\n");

    const int S = KDIM / 32;   // 32
    for (int s = 0; s < S; s++) {
        asm volatile("cp.async.wait_group 2;\n" ::: "memory");
        __syncthreads();
        // buffer (s+3)%4 was consumed in iteration s-1 -> safe
        if (s + 3 < S) load_stage((s + 3) & (STAGES - 1), (s + 3) * 32);
        asm volatile("cp.async.commit_group;\n");

        const uint32_t bb = sbase + (uint32_t)((s & (STAGES - 1)) * STAGEB);
#pragma unroll
        for (int kb = 0; kb < 2; kb++) {
            uint32_t Ahf[4][4], Alf[4][4];
#pragma unroll
            for (int mi = 0; mi < 4; mi++) {
                const uint32_t aa = bb + aoff[mi] + (uint32_t)((kb * 32 + ak2) ^ axr);
                LDSM_X4(Ahf[mi][0], Ahf[mi][1], Ahf[mi][2], Ahf[mi][3], aa);
                LDSM_X4(Alf[mi][0], Alf[mi][1], Alf[mi][2], Alf[mi][3], aa + SECB);
            }
#pragma unroll
            for (int gi = 0; gi < 4; gi++) {
                uint32_t Bf[4];
                const uint32_t ba = bb + boff[gi] + (uint32_t)((kb * 32 + bk2) ^ bxr);
                LDSM_X4(Bf[0], Bf[1], Bf[2], Bf[3], ba);
#pragma unroll
                for (int mi = 0; mi < 4; mi++)
#pragma unroll
                    for (int hf = 0; hf < 2; hf++) {
                        float* d = acc[mi][gi * 2 + hf];
                        MMA_F16(d, Ahf[mi], Bf[2 * hf], Bf[2 * hf + 1]);
                        MMA_F16(d, Alf[mi], Bf[2 * hf], Bf[2 * hf + 1]);
                    }
            }
        }
    }

    const int qr = lane >> 2;
    const int qc = (lane & 3) * 2;
    const int seg = blockIdx.x >> 3;   // MODE 1: 1024-col segment (CTA fully inside)

    // MODE 1 seg 0/1: fused per-head RMSNorm (warp col range = one 64-dim head)
    if (MODE == 1 && seg < 2) {
        const float* wn_ = (seg == 0) ? q0 : q1;
#pragma unroll
        for (int mi = 0; mi < 4; mi++)
#pragma unroll
            for (int rh = 0; rh < 2; rh++) {
                float ss = 0.0f;
#pragma unroll
                for (int ti = 0; ti < 8; ti++) {
                    float a = acc[mi][ti][2 * rh], b2 = acc[mi][ti][2 * rh + 1];
                    ss += a * a + b2 * b2;
                }
                ss += __shfl_xor_sync(0xffffffffu, ss, 1);
                ss += __shfl_xor_sync(0xffffffffu, ss, 2);
                const float sc = rsqrtf(ss * (1.0f / 64.0f) + 1e-6f);
#pragma unroll
                for (int ti = 0; ti < 8; ti++) {
                    acc[mi][ti][2 * rh]     *= sc * wn_[ti * 8 + qc];
                    acc[mi][ti][2 * rh + 1] *= sc * wn_[ti * 8 + qc + 1];
                }
            }
    }

#pragma unroll
    for (int mi = 0; mi < 4; mi++) {
#pragma unroll
        for (int ti = 0; ti < 8; ti++) {
            const int col = n0 + wn * 64 + ti * 8 + qc;
            float b0 = 0.f, b1 = 0.f;
            if (MODE == 1 && seg >= 3) {
                const float* bp = (seg == 3) ? q2 : (seg == 4) ? q3 : q4;
                const int cs = col & 1023;
                b0 = bp[cs]; b1 = bp[cs + 1];
            }
#pragma unroll
            for (int rh = 0; rh < 2; rh++) {
                const int row = m0 + wm * 64 + mi * 16 + rh * 8 + qr;
                float x0 = acc[mi][ti][2 * rh + 0];
                float x1 = acc[mi][ti][2 * rh + 1];
                if (MODE == 1) {
                    if (seg == 3)      { x0 = expf(x0 + b0); x1 = expf(x1 + b1); }
                    else if (seg >= 4) { x0 = 1.0f / (1.0f + expf(-(x0 + b0)));
                                         x1 = 1.0f / (1.0f + expf(-(x1 + b1))); }
                }
                *(float2*)&C[(size_t)row * ldc + col] = make_float2(x0, x1);
                if (MODE == 0) {
                    *(uint32_t*)&Chh[(size_t)row * ldc + col] = packh(x0, x1);
                    *(uint32_t*)&Cll[(size_t)row * ldc + col] = packhl(x0, x1);
                }
            }
        }
    }
}

// ---------------------------------------------------------------------------
// Chunk-parallel mLSTM scan (reads fused projection buffer, ld = 6144)
// ---------------------------------------------------------------------------
__global__ void __launch_bounds__(128, 4)
chunk_fwd(const float* __restrict__ pj,
          float* __restrict__ dC, float* __restrict__ dN, float* __restrict__ G)
{
    __shared__ float stage[2][4][64];

    const int tid = threadIdx.x;
    const int cid = blockIdx.x;
    const int j   = cid & (NCHUNK - 1);
    const int bh  = cid >> 6;
    const int b   = bh >> 4;
    const int h   = bh & 15;
    const size_t base6 = ((size_t)b * LL + (size_t)j * CHUNK) * NPJ + (size_t)h * 64;

    // k, v, i, f at segments 1,2,3,4
    const float* srcs[4] = { pj + base6 + 1024, pj + base6 + 2048,
                             pj + base6 + 3072, pj + base6 + 4096 };
    const int  arr = tid >> 4;
    const int  ch  = tid & 15;
    const bool loader = (tid < 64);
    const float* mySrc = srcs[loader ? arr : 0] + ch * 4;
    const uint32_t mydst0 = (uint32_t)__cvta_generic_to_shared(&stage[0][0][0]) + (arr * 64 + ch * 4) * 4;
    const uint32_t mydst1 = mydst0 + 4 * 64 * 4;

    if (loader) cp16(mydst0, mySrc);
    asm volatile("cp.async.commit_group;\n");

    const int r = tid >> 5;
    const int c = tid & 31;
    float C0[16], C1[16];
#pragma unroll
    for (int i = 0; i < 16; i++) { C0[i] = 0.0f; C1[i] = 0.0f; }
    float nreg = 0.0f, greg = 1.0f;

    for (int t = 0; t < CHUNK; t++) {
        asm volatile("cp.async.wait_group 0;\n" ::: "memory");
        __syncthreads();
        const int cur = t & 1;

        if (t + 1 < CHUNK && loader)
            cp16(cur ? mydst0 : mydst1, mySrc + (size_t)(t + 1) * NPJ);
        asm volatile("cp.async.commit_group;\n");

        const float* S   = &stage[cur][0][0];
        const float* ks  = S;
        const float* vs  = S + 64;
        const float* is_ = S + 128;
        const float* fs  = S + 192;

        float v0 = vs[c], v1 = vs[c + 32];

#pragma unroll
        for (int dd = 0; dd < 16; dd += 4) {
            int d = r * 16 + dd;
            float4 f4 = *(const float4*)&fs[d];
            float4 i4 = *(const float4*)&is_[d];
            float4 k4 = *(const float4*)&ks[d];
            float a0 = i4.x * k4.x, a1 = i4.y * k4.y, a2 = i4.z * k4.z, a3 = i4.w * k4.w;
            C0[dd+0] = fmaf(f4.x, C0[dd+0], a0 * v0); C1[dd+0] = fmaf(f4.x, C1[dd+0], a0 * v1);
            C0[dd+1] = fmaf(f4.y, C0[dd+1], a1 * v0); C1[dd+1] = fmaf(f4.y, C1[dd+1], a1 * v1);
            C0[dd+2] = fmaf(f4.z, C0[dd+2], a2 * v0); C1[dd+2] = fmaf(f4.z, C1[dd+2], a2 * v1);
            C0[dd+3] = fmaf(f4.w, C0[dd+3], a3 * v0); C1[dd+3] = fmaf(f4.w, C1[dd+3], a3 * v1);
        }

        if (tid < 64) {
            float ft = fs[tid];
            nreg = fmaf(ft, nreg, is_[tid] * ks[tid]);
            greg *= ft;
        }
        __syncthreads();
    }

    float* dCp = dC + (size_t)cid * 4096;
#pragma unroll
    for (int dd = 0; dd < 16; dd++) {
        dCp[(r * 16 + dd) * 64 + c]      = C0[dd];
        dCp[(r * 16 + dd) * 64 + c + 32] = C1[dd];
    }
    if (tid < 64) {
        dN[(size_t)cid * 64 + tid] = nreg;
        G [(size_t)cid * 64 + tid] = greg;
    }
}

__global__ void __launch_bounds__(128, 1)
chunk_carry(const float* __restrict__ dC, const float* __restrict__ dN,
            const float* __restrict__ G,
            float* __restrict__ Cst, float* __restrict__ Nst)
{
    __shared__ float gs[64], dns[64];
    const int tid = threadIdx.x;
    const int bh  = blockIdx.x;
    const int r = tid >> 5;
    const int c = tid & 31;

    float C0[16], C1[16];
#pragma unroll
    for (int i = 0; i < 16; i++) { C0[i] = 0.0f; C1[i] = 0.0f; }
    float n = 0.0f;

    for (int j = 0; j < NCHUNK; j++) {
        const size_t cid = (size_t)bh * NCHUNK + j;
        float* Cp = Cst + cid * 4096;
        const float* Dp = dC + cid * 4096;

        if (tid < 64) {
            Nst[cid * 64 + tid] = n;
            gs[tid]  = G [cid * 64 + tid];
            dns[tid] = dN[cid * 64 + tid];
        }
#pragma unroll
        for (int dd = 0; dd < 16; dd++) {
            Cp[(r * 16 + dd) * 64 + c]      = C0[dd];
            Cp[(r * 16 + dd) * 64 + c + 32] = C1[dd];
        }
        __syncthreads();
#pragma unroll
        for (int dd = 0; dd < 16; dd++) {
            float gd = gs[r * 16 + dd];
            C0[dd] = fmaf(gd, C0[dd], Dp[(r * 16 + dd) * 64 + c]);
            C1[dd] = fmaf(gd, C1[dd], Dp[(r * 16 + dd) * 64 + c + 32]);
        }
        if (tid < 64) n = fmaf(gs[tid], n, dns[tid]);
        __syncthreads();
    }
}

__global__ void __launch_bounds__(128, 4)
chunk_out(const float* __restrict__ pj, const float* __restrict__ xp,
          const float* __restrict__ Cst, const float* __restrict__ Nst,
          __half* __restrict__ hh, __half* __restrict__ hl)
{
    __shared__ float stage[2][7][64];
    __shared__ float red[4][64];
    __shared__ float denp[2];

    const int tid = threadIdx.x;
    const int cid = blockIdx.x;
    const int j   = cid & (NCHUNK - 1);
    const int bh  = cid >> 6;
    const int b   = bh >> 4;
    const int h   = bh & 15;
    const size_t base6 = ((size_t)b * LL + (size_t)j * CHUNK) * NPJ + (size_t)h * 64;
    const size_t base1 = ((size_t)b * LL + (size_t)j * CHUNK) * 1024 + (size_t)h * 64;
    const size_t baseg = ((size_t)b * LL + (size_t)j * CHUNK) * 2048 + 1024 + (size_t)h * 64;

    // q,k,v,i,f,o at segments 0..5; x_gate from xp
    const float* srcs[8] = { pj + base6,        pj + base6 + 1024, pj + base6 + 2048,
                             pj + base6 + 3072, pj + base6 + 4096, pj + base6 + 5120,
                             xp + baseg,        pj + base6 };

    const int  arr = tid >> 4;
    const int  ch  = tid & 15;
    const bool loader = (tid < 112);
    const float* mySrc    = srcs[arr] + ch * 4;
    const size_t mystride = (arr == 6) ? 2048 : NPJ;
    const uint32_t mydst0 = (uint32_t)__cvta_generic_to_shared(&stage[0][0][0]) + (arr * 64 + ch * 4) * 4;
    const uint32_t mydst1 = mydst0 + 7 * 64 * 4;

    if (loader) cp16(mydst0, mySrc);
    asm volatile("cp.async.commit_group;\n");

    const int r = tid >> 5;
    const int c = tid & 31;

    const float* Cp = Cst + (size_t)cid * 4096;
    float C0[16], C1[16];
#pragma unroll
    for (int dd = 0; dd < 16; dd++) {
        C0[dd] = Cp[(r * 16 + dd) * 64 + c];
        C1[dd] = Cp[(r * 16 + dd) * 64 + c + 32];
    }
    float nreg = (tid < 64) ? Nst[(size_t)cid * 64 + tid] : 0.0f;

    for (int t = 0; t < CHUNK; t++) {
        asm volatile("cp.async.wait_group 0;\n" ::: "memory");
        __syncthreads();
        const int cur = t & 1;

        if (t + 1 < CHUNK && loader)
            cp16(cur ? mydst0 : mydst1, mySrc + (size_t)(t + 1) * mystride);
        asm volatile("cp.async.commit_group;\n");

        const float* S   = &stage[cur][0][0];
        const float* qs  = S;
        const float* ks  = S + 64;
        const float* vs  = S + 128;
        const float* is_ = S + 192;
        const float* fs  = S + 256;
        const float* ogs = S + 320;
        const float* xgs = S + 384;

        float v0 = vs[c], v1 = vs[c + 32];
        float pn0 = 0.0f, pn1 = 0.0f;

#define ROWOP(ff, qq, aa, idx) { float _a = (aa);                              \
        C0[idx] = fmaf((ff), C0[idx], _a * v0); pn0 = fmaf((qq), C0[idx], pn0);\
        C1[idx] = fmaf((ff), C1[idx], _a * v1); pn1 = fmaf((qq), C1[idx], pn1); }

#pragma unroll
        for (int dd = 0; dd < 16; dd += 4) {
            int d = r * 16 + dd;
            float4 f4 = *(const float4*)&fs[d];
            float4 q4 = *(const float4*)&qs[d];
            float4 i4 = *(const float4*)&is_[d];
            float4 k4 = *(const float4*)&ks[d];
            ROWOP(f4.x, q4.x, i4.x * k4.x, dd + 0);
            ROWOP(f4.y, q4.y, i4.y * k4.y, dd + 1);
            ROWOP(f4.z, q4.z, i4.z * k4.z, dd + 2);
            ROWOP(f4.w, q4.w, i4.w * k4.w, dd + 3);
        }
#undef ROWOP

        red[r][c]      = pn0;
        red[r][c + 32] = pn1;

        if (tid < 64) {
            float a = is_[tid] * ks[tid];
            nreg = fmaf(fs[tid], nreg, a);
            float dp = qs[tid] * nreg;
#pragma unroll
            for (int o = 16; o; o >>= 1) dp += __shfl_xor_sync(0xffffffffu, dp, o);
            if ((tid & 31) == 0) denp[tid >> 5] = dp;
        }
        __syncthreads();

        if (tid < 64) {
            float num = red[0][tid] + red[1][tid] + red[2][tid] + red[3][tid];
            float den = fmaxf(denp[0] + denp[1], 1.0f);
            float ov  = (num / den) * ogs[tid] * (1.0f / (1.0f + expf(-xgs[tid])));
            __half h2 = __float2half_rn(ov);
            __half l2 = __float2half_rn(ov - __half2float(h2));
            hh[base1 + (size_t)t * 1024 + tid] = h2;
            hl[base1 + (size_t)t * 1024 + tid] = l2;
        }
    }
}

// ---------------------------------------------------------------------------
// Launch
// ---------------------------------------------------------------------------
extern "C" void kernel_launch(void* const* d_in, const int* in_sizes, int n_in,
                              void* d_out, int out_size)
{
    const float* x     = (const float*)d_in[0];
    const float* w_in  = (const float*)d_in[1];
    const float* w_q   = (const float*)d_in[2];
    const float* w_k   = (const float*)d_in[3];
    const float* w_v   = (const float*)d_in[4];
    const float* w_i   = (const float*)d_in[5];
    const float* b_i   = (const float*)d_in[6];
    const float* w_f   = (const float*)d_in[7];
    const float* b_f   = (const float*)d_in[8];
    const float* w_o   = (const float*)d_in[9];
    const float* b_o   = (const float*)d_in[10];
    const float* w_qn  = (const float*)d_in[11];
    const float* w_kn  = (const float*)d_in[12];
    const float* w_out = (const float*)d_in[13];
    float* out = (float*)d_out;

    float *xp, *pj, *dC, *dN, *G, *Cst, *Nst;
    __half *xh, *xl, *xph, *xpl, *hh, *hl, *wif, *w6f, *wof;
    cudaGetSymbolAddress((void**)&xp,  g_xp);
    cudaGetSymbolAddress((void**)&pj,  g_pj);
    cudaGetSymbolAddress((void**)&dC,  g_dC);
    cudaGetSymbolAddress((void**)&dN,  g_dN);
    cudaGetSymbolAddress((void**)&G,   g_G);
    cudaGetSymbolAddress((void**)&Cst, g_Cst);
    cudaGetSymbolAddress((void**)&Nst, g_Nst);
    cudaGetSymbolAddress((void**)&xh,  g_xh);
    cudaGetSymbolAddress((void**)&xl,  g_xl);
    cudaGetSymbolAddress((void**)&xph, g_xph);
    cudaGetSymbolAddress((void**)&xpl, g_xpl);
    cudaGetSymbolAddress((void**)&hh,  g_hh);
    cudaGetSymbolAddress((void**)&hl,  g_hl);
    cudaGetSymbolAddress((void**)&wif, g_wif);
    cudaGetSymbolAddress((void**)&w6f, g_w6f);
    cudaGetSymbolAddress((void**)&wof, g_wof);

    cudaFuncSetAttribute(gemm_f16<0>, cudaFuncAttributeMaxDynamicSharedMemorySize, GEMM_SMEM);
    cudaFuncSetAttribute(gemm_f16<1>, cudaFuncAttributeMaxDynamicSharedMemorySize, GEMM_SMEM);
    cudaFuncSetAttribute(gemm_f16<2>, cudaFuncAttributeMaxDynamicSharedMemorySize, GEMM_SMEM);

    // ---- pass 0: operand conversion ----
    const int NSQ4 = 1024 * 1024 / 4;
    split_h<<<(MROWS * 1024 / 4 + 255) / 256, 256>>>((const float4*)x, (uint2*)xh, (uint2*)xl, MROWS * 1024 / 4);
    cvt_h<<<(2048 * 1024 / 4 + 255) / 256, 256>>>((const float4*)w_in, (uint2*)wif, 2048 * 1024 / 4);
    const float* w6src[6] = { w_q, w_k, w_v, w_i, w_f, w_o };
    for (int t = 0; t < 6; t++)
        cvt_h<<<(NSQ4 + 255) / 256, 256>>>((const float4*)w6src[t],
                                           (uint2*)(w6f + (size_t)t * 1024 * 1024), NSQ4);
    cvt_h<<<(NSQ4 + 255) / 256, 256>>>((const float4*)w_out, (uint2*)wof, NSQ4);

    dim3 blk(128);

    // ---- in_proj: [8192,2048] = x @ w_in^T, + fp16 split of output ----
    gemm_f16<0><<<dim3(2048 / 128, MROWS / 128), blk, GEMM_SMEM>>>(
        xh, xl, 1024, wif, nullptr, nullptr, nullptr, nullptr, nullptr,
        xp, 2048, xph, xpl);

    // ---- fused 6-projection GEMM: [8192,6144] ----
    gemm_f16<1><<<dim3(NPJ / 128, MROWS / 128), blk, GEMM_SMEM>>>(
        xph, xpl, 2048, w6f, w_qn, w_kn, b_i, b_f, b_o,
        pj, NPJ, nullptr, nullptr);

    // ---- chunk-parallel scan ----
    chunk_fwd  <<<NCID, 128>>>(pj, dC, dN, G);
    chunk_carry<<<BB * NH, 128>>>(dC, dN, G, Cst, Nst);
    chunk_out  <<<NCID, 128>>>(pj, xp, Cst, Nst, hh, hl);

    // ---- output projection ----
    gemm_f16<2><<<dim3(1024 / 128, MROWS / 128), blk, GEMM_SMEM>>>(
        hh, hl, 1024, wof, nullptr, nullptr, nullptr, nullptr, nullptr,
        out, 1024, nullptr, nullptr);
}

// round 9
// speedup vs baseline: 5.1457x; 1.0213x over previous
#include <cuda_runtime.h>
#include <cuda_fp16.h>
#include <math.h>
#include <stdint.h>

// Problem constants
#define BB   2
#define LL   4096
#define DIMD 1024
#define NH   16
#define HD   64
#define MROWS (BB * LL)          // 8192
#define KDIM 1024
#define CHUNK  64
#define NCHUNK (LL / CHUNK)      // 64
#define NCID   (BB * NH * NCHUNK) // 2048
#define NPJ  6144                // fused projection width

// ---------------------------------------------------------------------------
// Scratch
// ---------------------------------------------------------------------------
__device__ float g_xp[(size_t)MROWS * 2048];
__device__ float g_pj[(size_t)MROWS * NPJ];   // q|k|v|i|f|o fused, ld=6144
// fp16 split operand buffers
__device__ __half g_xh [(size_t)MROWS * 1024];
__device__ __half g_xl [(size_t)MROWS * 1024];
__device__ __half g_xph[(size_t)MROWS * 2048];
__device__ __half g_xpl[(size_t)MROWS * 2048];
__device__ __half g_hh [(size_t)MROWS * 1024];
__device__ __half g_hl [(size_t)MROWS * 1024];
__device__ __half g_wif[(size_t)2048 * 1024];
__device__ __half g_w6f[(size_t)6 * 1024 * 1024];
__device__ __half g_wof[(size_t)1024 * 1024];
// chunked-scan scratch
__device__ float g_dC [(size_t)NCID * 4096];
__device__ float g_dN [(size_t)NCID * 64];
__device__ float g_G  [(size_t)NCID * 64];
__device__ float g_Cst[(size_t)NCID * 4096];
__device__ float g_Nst[(size_t)NCID * 64];

// ---------------------------------------------------------------------------
// helpers
// ---------------------------------------------------------------------------
__device__ __forceinline__ uint32_t packh(float x, float y) {
    __half hx = __float2half_rn(x);
    __half hy = __float2half_rn(y);
    return (uint32_t)__half_as_ushort(hx) | ((uint32_t)__half_as_ushort(hy) << 16);
}
__device__ __forceinline__ uint32_t packhl(float x, float y) {
    __half hx = __float2half_rn(x);
    __half hy = __float2half_rn(y);
    return packh(x - __half2float(hx), y - __half2float(hy));
}
__device__ __forceinline__ void cp16(uint32_t s, const void* g)
{
    asm volatile("cp.async.ca.shared.global [%0], [%1], 16;\n" :: "r"(s), "l"(g));
}

#define LDSM_X4(r0, r1, r2, r3, addr) \
    asm volatile("ldmatrix.sync.aligned.m8n8.x4.shared.b16 {%0,%1,%2,%3}, [%4];" \
                 : "=r"(r0), "=r"(r1), "=r"(r2), "=r"(r3) : "r"(addr))

#define MMA_F16(d, a, b0, b1) \
    asm volatile("mma.sync.aligned.m16n8k16.row.col.f32.f16.f16.f32 " \
                 "{%0,%1,%2,%3}, {%4,%5,%6,%7}, {%8,%9}, {%0,%1,%2,%3};" \
                 : "+f"((d)[0]), "+f"((d)[1]), "+f"((d)[2]), "+f"((d)[3]) \
                 : "r"((a)[0]), "r"((a)[1]), "r"((a)[2]), "r"((a)[3]), \
                   "r"(b0), "r"(b1))

// ---------------------------------------------------------------------------
// Pass 0a: fp32 -> (hi, lo) fp16 split (for x)
// ---------------------------------------------------------------------------
__global__ void split_h(const float4* __restrict__ s, uint2* __restrict__ hi,
                        uint2* __restrict__ lo, int n4)
{
    int i = blockIdx.x * 256 + threadIdx.x;
    if (i >= n4) return;
    float4 v = s[i];
    uint2 h, l;
    h.x = packh(v.x, v.y);  h.y = packh(v.z, v.w);
    l.x = packhl(v.x, v.y); l.y = packhl(v.z, v.w);
    hi[i] = h; lo[i] = l;
}

// Pass 0b: fp32 -> fp16 (single matrix)
__global__ void cvt_h(const float4* __restrict__ s, uint2* __restrict__ d, int n4)
{
    int i = blockIdx.x * 256 + threadIdx.x;
    if (i >= n4) return;
    float4 v = s[i];
    uint2 o;
    o.x = packh(v.x, v.y); o.y = packh(v.z, v.w);
    d[i] = o;
}

// Pass 0c: fp32 -> fp16 for the 6 projection weights in one launch.
// grid = (1024, 6); blockIdx.y selects the source matrix.
__global__ void cvt_h6(const float4* __restrict__ s0, const float4* __restrict__ s1,
                       const float4* __restrict__ s2, const float4* __restrict__ s3,
                       const float4* __restrict__ s4, const float4* __restrict__ s5,
                       uint2* __restrict__ d)
{
    const int n4 = 1024 * 1024 / 4;
    int i = blockIdx.x * 256 + threadIdx.x;
    if (i >= n4) return;
    const float4* s;
    switch (blockIdx.y) {
        case 0: s = s0; break; case 1: s = s1; break; case 2: s = s2; break;
        case 3: s = s3; break; case 4: s = s4; break; default: s = s5; break;
    }
    float4 v = s[i];
    uint2 o;
    o.x = packh(v.x, v.y); o.y = packh(v.z, v.w);
    d[(size_t)blockIdx.y * n4 + i] = o;
}

// ---------------------------------------------------------------------------
// cp.async pipelined fp16 2-MMA GEMM.
// C[M,N] = (Ah+Al)[M,K] @ B[N,K]^T, K=1024, CTA 128x128, warp 64x64, BK=32.
// smem/stage: Ah|Al|B, each 128 rows x 64B (SW64) = 24KB; 4 stages = 96KB,
// 2 CTAs/SM.
// R9: de-interleaved MMA chains (all Ah-MMAs for a gi, then all Al-MMAs) so
// the two RAW-dependent writes to each accumulator are ~8 MMAs apart, plus
// B-fragment double buffering. Numerics identical to R8.
// MODE 0: in_proj  -> fp32 C + fp16 hi/lo split outputs
// MODE 1: fused projections, N=6144, per-1024-col-segment epilogue
// MODE 2: plain fp32 C
// ---------------------------------------------------------------------------
#define STAGES 4
#define SECB   8192
#define STAGEB (3 * SECB)             // 24576
#define GEMM_SMEM (STAGES * STAGEB)   // 98304

template <int MODE>
__global__ void __launch_bounds__(128, 2)
gemm_f16(const __half* __restrict__ Ah, const __half* __restrict__ Al, int lda,
         const __half* __restrict__ B,
         const float* __restrict__ q0, const float* __restrict__ q1,
         const float* __restrict__ q2, const float* __restrict__ q3,
         const float* __restrict__ q4,
         float* __restrict__ C, int ldc,
         __half* __restrict__ Chh, __half* __restrict__ Cll)
{
    extern __shared__ __align__(128) char smem[];
    const uint32_t sbase = (uint32_t)__cvta_generic_to_shared(smem);

    const int tid  = threadIdx.x;
    const int w    = tid >> 5;
    const int lane = tid & 31;
    const int wm   = w & 1;          // M half (64 rows)
    const int wn   = w >> 1;         // N half (64 cols)

    const int m0 = blockIdx.y * 128;
    const int n0 = blockIdx.x * 128;

    const __half* Ahp = Ah + (size_t)m0 * lda;
    const __half* Alp = Al + (size_t)m0 * lda;
    const __half* Bp  = B  + (size_t)n0 * KDIM;

    // loader: 1536 16B chunks / stage, 12 per thread
    auto load_stage = [&](int buf, int k0) {
        const uint32_t db = sbase + (uint32_t)(buf * STAGEB);
#pragma unroll
        for (int i = 0; i < 12; i++) {
            const int ci  = tid + i * 128;
            const int sec = ci >> 9;          // 0=Ah 1=Al 2=B
            const int r   = (ci >> 2) & 127;
            const int kq  = ci & 3;
            const __half* gp;
            if      (sec == 0) gp = Ahp + (size_t)r * lda;
            else if (sec == 1) gp = Alp + (size_t)r * lda;
            else               gp = Bp  + (size_t)r * KDIM;
            gp += k0 + kq * 8;
            const uint32_t d = db + (uint32_t)(sec * SECB + r * 64 + ((kq * 16) ^ ((r * 8) & 0x30)));
            cp16(d, gp);
        }
    };

    // ldmatrix per-lane addressing (SW64)
    const int a_r  = (lane & 7) + ((lane >> 3) & 1) * 8;
    const int ak2  = ((lane >> 4) & 1) * 16;
    const uint32_t axr = (uint32_t)((a_r << 3) & 0x30);
    const int g    = lane >> 3;
    const int b_r  = ((g >> 1) * 8) + (lane & 7);
    const int bk2  = (g & 1) * 16;
    const uint32_t bxr = (uint32_t)((b_r << 3) & 0x30);

    uint32_t aoff[4], boff[4];
#pragma unroll
    for (int mi = 0; mi < 4; mi++) aoff[mi] = (uint32_t)((wm * 64 + mi * 16 + a_r) * 64);
#pragma unroll
    for (int gi = 0; gi < 4; gi++) boff[gi] = (uint32_t)(2 * SECB + (wn * 64 + gi * 16 + b_r) * 64);

    float acc[4][8][4] = {};

    load_stage(0, 0);
    asm volatile("cp.async.commit_group;\n");
    load_stage(1, 32);
    asm volatile("cp.async.commit_group;\n");
    load_stage(2, 64);
    asm volatile("cp.async.commit_group;\n");

    const int S = KDIM / 32;   // 32
    for (int s = 0; s < S; s++) {
        asm volatile("cp.async.wait_group 2;\n" ::: "memory");
        __syncthreads();
        // buffer (s+3)%4 was consumed in iteration s-1 -> safe
        if (s + 3 < S) load_stage((s + 3) & (STAGES - 1), (s + 3) * 32);
        asm volatile("cp.async.commit_group;\n");

        const uint32_t bb = sbase + (uint32_t)((s & (STAGES - 1)) * STAGEB);
#pragma unroll
        for (int kb = 0; kb < 2; kb++) {
            uint32_t Ahf[4][4], Alf[4][4];
#pragma unroll
            for (int mi = 0; mi < 4; mi++) {
                const uint32_t aa = bb + aoff[mi] + (uint32_t)((kb * 32 + ak2) ^ axr);
                LDSM_X4(Ahf[mi][0], Ahf[mi][1], Ahf[mi][2], Ahf[mi][3], aa);
                LDSM_X4(Alf[mi][0], Alf[mi][1], Alf[mi][2], Alf[mi][3], aa + SECB);
            }
            uint32_t Bf[2][4];
            {
                const uint32_t ba0 = bb + boff[0] + (uint32_t)((kb * 32 + bk2) ^ bxr);
                LDSM_X4(Bf[0][0], Bf[0][1], Bf[0][2], Bf[0][3], ba0);
            }
#pragma unroll
            for (int gi = 0; gi < 4; gi++) {
                if (gi < 3) {
                    const uint32_t ban = bb + boff[gi + 1] + (uint32_t)((kb * 32 + bk2) ^ bxr);
                    uint32_t* Bn = Bf[(gi + 1) & 1];
                    LDSM_X4(Bn[0], Bn[1], Bn[2], Bn[3], ban);
                }
                const uint32_t* Bc = Bf[gi & 1];
                // pass 1: all Ah-MMAs (8 independent accumulators)
#pragma unroll
                for (int mi = 0; mi < 4; mi++)
#pragma unroll
                    for (int hf = 0; hf < 2; hf++)
                        MMA_F16(acc[mi][gi * 2 + hf], Ahf[mi], Bc[2 * hf], Bc[2 * hf + 1]);
                // pass 2: all Al-MMAs (each is now ~8 MMAs after its RAW producer)
#pragma unroll
                for (int mi = 0; mi < 4; mi++)
#pragma unroll
                    for (int hf = 0; hf < 2; hf++)
                        MMA_F16(acc[mi][gi * 2 + hf], Alf[mi], Bc[2 * hf], Bc[2 * hf + 1]);
            }
        }
    }

    const int qr = lane >> 2;
    const int qc = (lane & 3) * 2;
    const int seg = blockIdx.x >> 3;   // MODE 1: 1024-col segment

    // MODE 1 seg 0/1: fused per-head RMSNorm (warp col range = one 64-dim head)
    if (MODE == 1 && seg < 2) {
        const float* wn_ = (seg == 0) ? q0 : q1;
#pragma unroll
        for (int mi = 0; mi < 4; mi++)
#pragma unroll
            for (int rh = 0; rh < 2; rh++) {
                float ss = 0.0f;
#pragma unroll
                for (int ti = 0; ti < 8; ti++) {
                    float a = acc[mi][ti][2 * rh], b2 = acc[mi][ti][2 * rh + 1];
                    ss += a * a + b2 * b2;
                }
                ss += __shfl_xor_sync(0xffffffffu, ss, 1);
                ss += __shfl_xor_sync(0xffffffffu, ss, 2);
                const float sc = rsqrtf(ss * (1.0f / 64.0f) + 1e-6f);
#pragma unroll
                for (int ti = 0; ti < 8; ti++) {
                    acc[mi][ti][2 * rh]     *= sc * wn_[ti * 8 + qc];
                    acc[mi][ti][2 * rh + 1] *= sc * wn_[ti * 8 + qc + 1];
                }
            }
    }

#pragma unroll
    for (int mi = 0; mi < 4; mi++) {
#pragma unroll
        for (int ti = 0; ti < 8; ti++) {
            const int col = n0 + wn * 64 + ti * 8 + qc;
            float b0 = 0.f, b1 = 0.f;
            if (MODE == 1 && seg >= 3) {
                const float* bp = (seg == 3) ? q2 : (seg == 4) ? q3 : q4;
                const int cs = col & 1023;
                b0 = bp[cs]; b1 = bp[cs + 1];
            }
#pragma unroll
            for (int rh = 0; rh < 2; rh++) {
                const int row = m0 + wm * 64 + mi * 16 + rh * 8 + qr;
                float x0 = acc[mi][ti][2 * rh + 0];
                float x1 = acc[mi][ti][2 * rh + 1];
                if (MODE == 1) {
                    if (seg == 3)      { x0 = expf(x0 + b0); x1 = expf(x1 + b1); }
                    else if (seg >= 4) { x0 = 1.0f / (1.0f + expf(-(x0 + b0)));
                                         x1 = 1.0f / (1.0f + expf(-(x1 + b1))); }
                }
                *(float2*)&C[(size_t)row * ldc + col] = make_float2(x0, x1);
                if (MODE == 0) {
                    *(uint32_t*)&Chh[(size_t)row * ldc + col] = packh(x0, x1);
                    *(uint32_t*)&Cll[(size_t)row * ldc + col] = packhl(x0, x1);
                }
            }
        }
    }
}

// ---------------------------------------------------------------------------
// Chunk-parallel mLSTM scan (reads fused projection buffer, ld = 6144)
// ---------------------------------------------------------------------------
__global__ void __launch_bounds__(128, 4)
chunk_fwd(const float* __restrict__ pj,
          float* __restrict__ dC, float* __restrict__ dN, float* __restrict__ G)
{
    __shared__ float stage[2][4][64];

    const int tid = threadIdx.x;
    const int cid = blockIdx.x;
    const int j   = cid & (NCHUNK - 1);
    const int bh  = cid >> 6;
    const int b   = bh >> 4;
    const int h   = bh & 15;
    const size_t base6 = ((size_t)b * LL + (size_t)j * CHUNK) * NPJ + (size_t)h * 64;

    // k, v, i, f at segments 1,2,3,4
    const float* srcs[4] = { pj + base6 + 1024, pj + base6 + 2048,
                             pj + base6 + 3072, pj + base6 + 4096 };
    const int  arr = tid >> 4;
    const int  ch  = tid & 15;
    const bool loader = (tid < 64);
    const float* mySrc = srcs[loader ? arr : 0] + ch * 4;
    const uint32_t mydst0 = (uint32_t)__cvta_generic_to_shared(&stage[0][0][0]) + (arr * 64 + ch * 4) * 4;
    const uint32_t mydst1 = mydst0 + 4 * 64 * 4;

    if (loader) cp16(mydst0, mySrc);
    asm volatile("cp.async.commit_group;\n");

    const int r = tid >> 5;
    const int c = tid & 31;
    float C0[16], C1[16];
#pragma unroll
    for (int i = 0; i < 16; i++) { C0[i] = 0.0f; C1[i] = 0.0f; }
    float nreg = 0.0f, greg = 1.0f;

    for (int t = 0; t < CHUNK; t++) {
        asm volatile("cp.async.wait_group 0;\n" ::: "memory");
        __syncthreads();
        const int cur = t & 1;

        if (t + 1 < CHUNK && loader)
            cp16(cur ? mydst0 : mydst1, mySrc + (size_t)(t + 1) * NPJ);
        asm volatile("cp.async.commit_group;\n");

        const float* S   = &stage[cur][0][0];
        const float* ks  = S;
        const float* vs  = S + 64;
        const float* is_ = S + 128;
        const float* fs  = S + 192;

        float v0 = vs[c], v1 = vs[c + 32];

#pragma unroll
        for (int dd = 0; dd < 16; dd += 4) {
            int d = r * 16 + dd;
            float4 f4 = *(const float4*)&fs[d];
            float4 i4 = *(const float4*)&is_[d];
            float4 k4 = *(const float4*)&ks[d];
            float a0 = i4.x * k4.x, a1 = i4.y * k4.y, a2 = i4.z * k4.z, a3 = i4.w * k4.w;
            C0[dd+0] = fmaf(f4.x, C0[dd+0], a0 * v0); C1[dd+0] = fmaf(f4.x, C1[dd+0], a0 * v1);
            C0[dd+1] = fmaf(f4.y, C0[dd+1], a1 * v0); C1[dd+1] = fmaf(f4.y, C1[dd+1], a1 * v1);
            C0[dd+2] = fmaf(f4.z, C0[dd+2], a2 * v0); C1[dd+2] = fmaf(f4.z, C1[dd+2], a2 * v1);
            C0[dd+3] = fmaf(f4.w, C0[dd+3], a3 * v0); C1[dd+3] = fmaf(f4.w, C1[dd+3], a3 * v1);
        }

        if (tid < 64) {
            float ft = fs[tid];
            nreg = fmaf(ft, nreg, is_[tid] * ks[tid]);
            greg *= ft;
        }
        __syncthreads();
    }

    float* dCp = dC + (size_t)cid * 4096;
#pragma unroll
    for (int dd = 0; dd < 16; dd++) {
        dCp[(r * 16 + dd) * 64 + c]      = C0[dd];
        dCp[(r * 16 + dd) * 64 + c + 32] = C1[dd];
    }
    if (tid < 64) {
        dN[(size_t)cid * 64 + tid] = nreg;
        G [(size_t)cid * 64 + tid] = greg;
    }
}

__global__ void __launch_bounds__(128, 1)
chunk_carry(const float* __restrict__ dC, const float* __restrict__ dN,
            const float* __restrict__ G,
            float* __restrict__ Cst, float* __restrict__ Nst)
{
    __shared__ float gs[64], dns[64];
    const int tid = threadIdx.x;
    const int bh  = blockIdx.x;
    const int r = tid >> 5;
    const int c = tid & 31;

    float C0[16], C1[16];
#pragma unroll
    for (int i = 0; i < 16; i++) { C0[i] = 0.0f; C1[i] = 0.0f; }
    float n = 0.0f;

    for (int j = 0; j < NCHUNK; j++) {
        const size_t cid = (size_t)bh * NCHUNK + j;
        float* Cp = Cst + cid * 4096;
        const float* Dp = dC + cid * 4096;

        if (tid < 64) {
            Nst[cid * 64 + tid] = n;
            gs[tid]  = G [cid * 64 + tid];
            dns[tid] = dN[cid * 64 + tid];
        }
#pragma unroll
        for (int dd = 0; dd < 16; dd++) {
            Cp[(r * 16 + dd) * 64 + c]      = C0[dd];
            Cp[(r * 16 + dd) * 64 + c + 32] = C1[dd];
        }
        __syncthreads();
#pragma unroll
        for (int dd = 0; dd < 16; dd++) {
            float gd = gs[r * 16 + dd];
            C0[dd] = fmaf(gd, C0[dd], Dp[(r * 16 + dd) * 64 + c]);
            C1[dd] = fmaf(gd, C1[dd], Dp[(r * 16 + dd) * 64 + c + 32]);
        }
        if (tid < 64) n = fmaf(gs[tid], n, dns[tid]);
        __syncthreads();
    }
}

__global__ void __launch_bounds__(128, 4)
chunk_out(const float* __restrict__ pj, const float* __restrict__ xp,
          const float* __restrict__ Cst, const float* __restrict__ Nst,
          __half* __restrict__ hh, __half* __restrict__ hl)
{
    __shared__ float stage[2][7][64];
    __shared__ float red[4][64];
    __shared__ float denp[2];

    const int tid = threadIdx.x;
    const int cid = blockIdx.x;
    const int j   = cid & (NCHUNK - 1);
    const int bh  = cid >> 6;
    const int b   = bh >> 4;
    const int h   = bh & 15;
    const size_t base6 = ((size_t)b * LL + (size_t)j * CHUNK) * NPJ + (size_t)h * 64;
    const size_t base1 = ((size_t)b * LL + (size_t)j * CHUNK) * 1024 + (size_t)h * 64;
    const size_t baseg = ((size_t)b * LL + (size_t)j * CHUNK) * 2048 + 1024 + (size_t)h * 64;

    // q,k,v,i,f,o at segments 0..5; x_gate from xp
    const float* srcs[8] = { pj + base6,        pj + base6 + 1024, pj + base6 + 2048,
                             pj + base6 + 3072, pj + base6 + 4096, pj + base6 + 5120,
                             xp + baseg,        pj + base6 };

    const int  arr = tid >> 4;
    const int  ch  = tid & 15;
    const bool loader = (tid < 112);
    const float* mySrc    = srcs[arr] + ch * 4;
    const size_t mystride = (arr == 6) ? 2048 : NPJ;
    const uint32_t mydst0 = (uint32_t)__cvta_generic_to_shared(&stage[0][0][0]) + (arr * 64 + ch * 4) * 4;
    const uint32_t mydst1 = mydst0 + 7 * 64 * 4;

    if (loader) cp16(mydst0, mySrc);
    asm volatile("cp.async.commit_group;\n");

    const int r = tid >> 5;
    const int c = tid & 31;

    const float* Cp = Cst + (size_t)cid * 4096;
    float C0[16], C1[16];
#pragma unroll
    for (int dd = 0; dd < 16; dd++) {
        C0[dd] = Cp[(r * 16 + dd) * 64 + c];
        C1[dd] = Cp[(r * 16 + dd) * 64 + c + 32];
    }
    float nreg = (tid < 64) ? Nst[(size_t)cid * 64 + tid] : 0.0f;

    for (int t = 0; t < CHUNK; t++) {
        asm volatile("cp.async.wait_group 0;\n" ::: "memory");
        __syncthreads();
        const int cur = t & 1;

        if (t + 1 < CHUNK && loader)
            cp16(cur ? mydst0 : mydst1, mySrc + (size_t)(t + 1) * mystride);
        asm volatile("cp.async.commit_group;\n");

        const float* S   = &stage[cur][0][0];
        const float* qs  = S;
        const float* ks  = S + 64;
        const float* vs  = S + 128;
        const float* is_ = S + 192;
        const float* fs  = S + 256;
        const float* ogs = S + 320;
        const float* xgs = S + 384;

        float v0 = vs[c], v1 = vs[c + 32];
        float pn0 = 0.0f, pn1 = 0.0f;

#define ROWOP(ff, qq, aa, idx) { float _a = (aa);                              \
        C0[idx] = fmaf((ff), C0[idx], _a * v0); pn0 = fmaf((qq), C0[idx], pn0);\
        C1[idx] = fmaf((ff), C1[idx], _a * v1); pn1 = fmaf((qq), C1[idx], pn1); }

#pragma unroll
        for (int dd = 0; dd < 16; dd += 4) {
            int d = r * 16 + dd;
            float4 f4 = *(const float4*)&fs[d];
            float4 q4 = *(const float4*)&qs[d];
            float4 i4 = *(const float4*)&is_[d];
            float4 k4 = *(const float4*)&ks[d];
            ROWOP(f4.x, q4.x, i4.x * k4.x, dd + 0);
            ROWOP(f4.y, q4.y, i4.y * k4.y, dd + 1);
            ROWOP(f4.z, q4.z, i4.z * k4.z, dd + 2);
            ROWOP(f4.w, q4.w, i4.w * k4.w, dd + 3);
        }
#undef ROWOP

        red[r][c]      = pn0;
        red[r][c + 32] = pn1;

        if (tid < 64) {
            float a = is_[tid] * ks[tid];
            nreg = fmaf(fs[tid], nreg, a);
            float dp = qs[tid] * nreg;
#pragma unroll
            for (int o = 16; o; o >>= 1) dp += __shfl_xor_sync(0xffffffffu, dp, o);
            if ((tid & 31) == 0) denp[tid >> 5] = dp;
        }
        __syncthreads();

        if (tid < 64) {
            float num = red[0][tid] + red[1][tid] + red[2][tid] + red[3][tid];
            float den = fmaxf(denp[0] + denp[1], 1.0f);
            float ov  = (num / den) * ogs[tid] * (1.0f / (1.0f + expf(-xgs[tid])));
            __half h2 = __float2half_rn(ov);
            __half l2 = __float2half_rn(ov - __half2float(h2));
            hh[base1 + (size_t)t * 1024 + tid] = h2;
            hl[base1 + (size_t)t * 1024 + tid] = l2;
        }
    }
}

// ---------------------------------------------------------------------------
// Launch
// ---------------------------------------------------------------------------
extern "C" void kernel_launch(void* const* d_in, const int* in_sizes, int n_in,
                              void* d_out, int out_size)
{
    const float* x     = (const float*)d_in[0];
    const float* w_in  = (const float*)d_in[1];
    const float* w_q   = (const float*)d_in[2];
    const float* w_k   = (const float*)d_in[3];
    const float* w_v   = (const float*)d_in[4];
    const float* w_i   = (const float*)d_in[5];
    const float* b_i   = (const float*)d_in[6];
    const float* w_f   = (const float*)d_in[7];
    const float* b_f   = (const float*)d_in[8];
    const float* w_o   = (const float*)d_in[9];
    const float* b_o   = (const float*)d_in[10];
    const float* w_qn  = (const float*)d_in[11];
    const float* w_kn  = (const float*)d_in[12];
    const float* w_out = (const float*)d_in[13];
    float* out = (float*)d_out;

    float *xp, *pj, *dC, *dN, *G, *Cst, *Nst;
    __half *xh, *xl, *xph, *xpl, *hh, *hl, *wif, *w6f, *wof;
    cudaGetSymbolAddress((void**)&xp,  g_xp);
    cudaGetSymbolAddress((void**)&pj,  g_pj);
    cudaGetSymbolAddress((void**)&dC,  g_dC);
    cudaGetSymbolAddress((void**)&dN,  g_dN);
    cudaGetSymbolAddress((void**)&G,   g_G);
    cudaGetSymbolAddress((void**)&Cst, g_Cst);
    cudaGetSymbolAddress((void**)&Nst, g_Nst);
    cudaGetSymbolAddress((void**)&xh,  g_xh);
    cudaGetSymbolAddress((void**)&xl,  g_xl);
    cudaGetSymbolAddress((void**)&xph, g_xph);
    cudaGetSymbolAddress((void**)&xpl, g_xpl);
    cudaGetSymbolAddress((void**)&hh,  g_hh);
    cudaGetSymbolAddress((void**)&hl,  g_hl);
    cudaGetSymbolAddress((void**)&wif, g_wif);
    cudaGetSymbolAddress((void**)&w6f, g_w6f);
    cudaGetSymbolAddress((void**)&wof, g_wof);

    cudaFuncSetAttribute(gemm_f16<0>, cudaFuncAttributeMaxDynamicSharedMemorySize, GEMM_SMEM);
    cudaFuncSetAttribute(gemm_f16<1>, cudaFuncAttributeMaxDynamicSharedMemorySize, GEMM_SMEM);
    cudaFuncSetAttribute(gemm_f16<2>, cudaFuncAttributeMaxDynamicSharedMemorySize, GEMM_SMEM);

    // ---- pass 0: operand conversion (4 launches; fused gemm = launch #6 for ncu) ----
    split_h<<<(MROWS * 1024 / 4 + 255) / 256, 256>>>((const float4*)x, (uint2*)xh, (uint2*)xl, MROWS * 1024 / 4);
    cvt_h<<<(2048 * 1024 / 4 + 255) / 256, 256>>>((const float4*)w_in, (uint2*)wif, 2048 * 1024 / 4);
    cvt_h6<<<dim3(1024, 6), 256>>>((const float4*)w_q, (const float4*)w_k, (const float4*)w_v,
                                   (const float4*)w_i, (const float4*)w_f, (const float4*)w_o,
                                   (uint2*)w6f);
    cvt_h<<<(1024 * 1024 / 4 + 255) / 256, 256>>>((const float4*)w_out, (uint2*)wof, 1024 * 1024 / 4);

    dim3 blk(128);

    // ---- in_proj: [8192,2048] = x @ w_in^T, + fp16 split of output ----
    gemm_f16<0><<<dim3(2048 / 128, MROWS / 128), blk, GEMM_SMEM>>>(
        xh, xl, 1024, wif, nullptr, nullptr, nullptr, nullptr, nullptr,
        xp, 2048, xph, xpl);

    // ---- fused 6-projection GEMM: [8192,6144] (launch #6 -> profiled) ----
    gemm_f16<1><<<dim3(NPJ / 128, MROWS / 128), blk, GEMM_SMEM>>>(
        xph, xpl, 2048, w6f, w_qn, w_kn, b_i, b_f, b_o,
        pj, NPJ, nullptr, nullptr);

    // ---- chunk-parallel scan ----
    chunk_fwd  <<<NCID, 128>>>(pj, dC, dN, G);
    chunk_carry<<<BB * NH, 128>>>(dC, dN, G, Cst, Nst);
    chunk_out  <<<NCID, 128>>>(pj, xp, Cst, Nst, hh, hl);

    // ---- output projection ----
    gemm_f16<2><<<dim3(1024 / 128, MROWS / 128), blk, GEMM_SMEM>>>(
        hh, hl, 1024, wof, nullptr, nullptr, nullptr, nullptr, nullptr,
        out, 1024, nullptr, nullptr);
}